// round 6
// baseline (speedup 1.0000x reference)
#include <cuda_runtime.h>
#include <math.h>
#include <stdint.h>

#define T_STEPS 128
#define BATCH   128
#define SAMP    8
#define DIN     64
#define RDIM    256
#define ZDIM    128
#define HDIM    512
#define BS      1024
#define TB      16384
#define NTHR    512

#define DT       0.05f
#define SQRT_DT  0.22360679774997896f
#define LOG_2PI  1.8378770664093453f

// ---------------- scratch ---------------------------------------------------
__device__ __align__(16) float g_Hh[TB * HDIM];
__device__ __align__(16) float g_Hhpos[TB * HDIM];
__device__ __align__(16) float g_Hph[TB * HDIM];
__device__ __align__(16) float g_Hf[TB * HDIM];
__device__ __align__(16) float g_diff[TB * ZDIM];
__device__ __align__(16) float g_Mt[T_STEPS * BATCH];
__device__ __align__(16) float g_z[BS * ZDIM];
// tf32-preconverted weights (bits stored in float)
__device__ __align__(16) float g_Wd2t[HDIM * ZDIM];
__device__ __align__(16) float g_Wp1zt[ZDIM * HDIM];
__device__ __align__(16) float g_Wd1zt[ZDIM * HDIM];
__device__ __align__(16) float g_Wp2t[HDIM * ZDIM];
__device__ float g_kldpart[T_STEPS * 64];
__device__ float g_reconpart[T_STEPS * 64];
__device__ int g_flag[64];   // drift -> p: z(t+1) published
__device__ int g_ack[64];    // p -> drift: z(t+1) consumed

__device__ __forceinline__ float4 ldcg4(const float* p) { return __ldcg((const float4*)p); }
__device__ __forceinline__ float2 ldcg2(const float* p) { return __ldcg((const float2*)p); }
__device__ __forceinline__ unsigned f2tf(float f) {
    unsigned r; asm("cvt.rna.tf32.f32 %0, %1;" : "=r"(r) : "f"(f)); return r;
}
#define FU(x)  __float_as_uint(x)
#define UF(x)  __uint_as_float(x)

__device__ __forceinline__ void mma8(float c[4], const unsigned a[4],
                                     unsigned b0, unsigned b1)
{
    asm volatile(
        "mma.sync.aligned.m16n8k8.row.col.f32.tf32.tf32.f32 "
        "{%0,%1,%2,%3}, {%4,%5,%6,%7}, {%8,%9}, {%0,%1,%2,%3};"
        : "+f"(c[0]), "+f"(c[1]), "+f"(c[2]), "+f"(c[3])
        : "r"(a[0]), "r"(a[1]), "r"(a[2]), "r"(a[3]), "r"(b0), "r"(b1));
}

// ---------------- z0 --------------------------------------------------------
__global__ void z0_kernel(const float* __restrict__ cov,
                          const float* __restrict__ Wc1, const float* __restrict__ bc1,
                          const float* __restrict__ Wc2, const float* __restrict__ bc2)
{
    int b = blockIdx.x;
    int tid = threadIdx.x;  // 128
    __shared__ float sc[32];
    __shared__ float shh[64];
    if (tid < 32) sc[tid] = cov[b * 32 + tid];
    __syncthreads();
    if (tid < 64) {
        float acc = bc1[tid];
        #pragma unroll
        for (int c = 0; c < 32; c++) acc = fmaf(sc[c], Wc1[c * 64 + tid], acc);
        shh[tid] = fmaxf(acc, 0.f);
    }
    __syncthreads();
    float acc = bc2[tid];
    #pragma unroll
    for (int k = 0; k < 64; k++) acc = fmaf(shh[k], Wc2[k * 128 + tid], acc);
    float z = tanhf(acc);
    #pragma unroll
    for (int s = 0; s < SAMP; s++)
        g_z[(b * SAMP + s) * ZDIM + tid] = z;
}

// ---------------- Mt --------------------------------------------------------
__global__ void mt_kernel(const float* __restrict__ M)
{
    int i = blockIdx.x * blockDim.x + threadIdx.x;
    const float4* p = (const float4*)(M + (size_t)i * DIN);
    float s = 0.f;
    #pragma unroll
    for (int j = 0; j < DIN / 4; j++) { float4 v = p[j]; s += v.x + v.y + v.z + v.w; }
    g_Mt[i] = s * (1.f / (float)DIN);
}

// ---------------- weight tf32 pre-conversion --------------------------------
__global__ void cvt_weights(const float* __restrict__ Wd2, const float* __restrict__ Wp1,
                            const float* __restrict__ Wd1, const float* __restrict__ Wp2)
{
    int i = blockIdx.x * 256 + threadIdx.x;   // 65536 each
    g_Wd2t[i]  = UF(f2tf(Wd2[i]));
    g_Wp1zt[i] = UF(f2tf(Wp1[RDIM * HDIM + i]));
    g_Wd1zt[i] = UF(f2tf(Wd1[RDIM * HDIM + i]));
    g_Wp2t[i]  = UF(f2tf(Wp2[i]));
}

// ---------------- generic fp32 GEMM (precompute only) ----------------------
template<int ACT, bool SUMA>
__global__ void gemm_f32(const float* __restrict__ A, const float* __restrict__ A2,
                         const float* __restrict__ W, const float* __restrict__ bias,
                         float* __restrict__ C, int M, int N, int K)
{
    __shared__ float sA[64][33];
    __shared__ float sB[32][68];
    const int bm = blockIdx.y * 64;
    const int bn = blockIdx.x * 64;
    const int tid = threadIdx.x;
    const int tx = tid & 15;
    const int ty = tid >> 4;
    float acc[4][4] = {};
    for (int k0 = 0; k0 < K; k0 += 32) {
        #pragma unroll
        for (int l = 0; l < 2; l++) {
            int v  = tid + l * 256;
            int r  = v >> 3;
            int c4 = (v & 7) * 4;
            float4 av = *(const float4*)&A[(size_t)(bm + r) * K + k0 + c4];
            if (SUMA) {
                float4 b4 = *(const float4*)&A2[(size_t)(bm + r) * K + k0 + c4];
                av.x += b4.x; av.y += b4.y; av.z += b4.z; av.w += b4.w;
            }
            sA[r][c4 + 0] = av.x; sA[r][c4 + 1] = av.y;
            sA[r][c4 + 2] = av.z; sA[r][c4 + 3] = av.w;
        }
        #pragma unroll
        for (int l = 0; l < 2; l++) {
            int v  = tid + l * 256;
            int r  = v >> 4;
            int c4 = (v & 15) * 4;
            *(float4*)&sB[r][c4] = *(const float4*)&W[(size_t)(k0 + r) * N + bn + c4];
        }
        __syncthreads();
        #pragma unroll
        for (int k = 0; k < 32; k++) {
            float a[4];
            #pragma unroll
            for (int i = 0; i < 4; i++) a[i] = sA[ty * 4 + i][k];
            float4 bv = *(const float4*)&sB[k][tx * 4];
            #pragma unroll
            for (int i = 0; i < 4; i++) {
                acc[i][0] = fmaf(a[i], bv.x, acc[i][0]);
                acc[i][1] = fmaf(a[i], bv.y, acc[i][1]);
                acc[i][2] = fmaf(a[i], bv.z, acc[i][2]);
                acc[i][3] = fmaf(a[i], bv.w, acc[i][3]);
            }
        }
        __syncthreads();
    }
    #pragma unroll
    for (int i = 0; i < 4; i++) {
        int r = bm + ty * 4 + i;
        #pragma unroll
        for (int j = 0; j < 4; j++) {
            int c = bn + tx * 4 + j;
            float v = acc[i][j] + (bias ? bias[c] : 0.f);
            if (ACT == 1) v = fmaxf(v, 0.f);
            if (ACT == 2) v = expf(v);
            C[(size_t)r * N + c] = v;
        }
    }
}

// ================= barrier-free pairwise scan ===============================
// Block 2g: drift for rows g*16..+16 (z smem-resident across all T).
// Block 2g+1: p-head/NLL for the same rows (consumes z(t+1) via L2+flag).

// smem float offsets (union across uses)
#define ZB   0        /* z tf32, chunked [4][16][36]            */
#define HZB  2304     /* Hz/Hpz 128-col group, [4][16][36] fp32 */
#define BBF  4608     /* B tile [32][136]                        */
#define SAP  8960     /* drift A_p / p-head A  [16][36]          */
#define SAQ  9536     /* drift A_q             [16][36]          */
#define SH_TOT 10112
#define QX   BBF      /* q fragment exchange [16][132] (post-MMA) */
#define LVO  BBF      /* logvar exchange [16][68] (post-MMA)      */
#define REDO SAP      /* reduction [512] (post-staging)           */

__device__ void drift_step(int t, const float* __restrict__ bd2,
                           const float* __restrict__ noise,
                           float* sh, float zr[8], int gidx)
{
    const int tid = threadIdx.x;
    const int w = tid >> 5, lane = tid & 31, gg = lane >> 2, tig = lane & 3;
    const int r0 = gidx * 16;
    const int isp = (w < 8);
    const int n0 = (w & 7) * 16;
    const size_t hb = (size_t)t * BATCH * HDIM;
    float acc0[4] = {0.f,0.f,0.f,0.f}, acc1[4] = {0.f,0.f,0.f,0.f};

    for (int np = 0; np < 4; np++) {
        // ---- Hz pass: Hz[:, np*128 .. np*128+128) = z @ Wd1z ----
        float ahz[4] = {0.f,0.f,0.f,0.f};
        for (int kc = 0; kc < 4; kc++) {
            __syncthreads();
            #pragma unroll
            for (int l = 0; l < 2; l++) {
                int v = tid + l * 512; int r = v >> 5; int c4 = (v & 31) * 4;
                *(uint4*)&sh[BBF + r * 136 + c4] =
                    *(const uint4*)&g_Wd1zt[(size_t)(kc * 32 + r) * HDIM + np * 128 + c4];
            }
            __syncthreads();
            const float* pA = sh + ZB + kc * 576 + gg * 36 + tig;
            const float* pB = sh + BBF + tig * 136 + w * 8 + gg;
            #pragma unroll
            for (int kk = 0; kk < 4; kk++) {
                unsigned a[4] = { FU(pA[kk*8]), FU(pA[kk*8 + 288]),
                                  FU(pA[kk*8 + 4]), FU(pA[kk*8 + 292]) };
                mma8(ahz, a, FU(pB[kk*8*136]), FU(pB[(kk*8 + 4)*136]));
            }
        }
        {   // write Hz fragments (local cols 0..127) to HZB (chunked fp32)
            int cl = w * 8 + 2 * tig;
            int base = HZB + (cl >> 5) * 576 + gg * 36 + (cl & 31);
            sh[base]       = ahz[0];
            sh[base + 1]   = ahz[1];
            sh[base + 288] = ahz[2];
            sh[base + 289] = ahz[3];
        }
        // ---- drift chunks using these 128 Hz cols ----
        for (int kc2 = 0; kc2 < 4; kc2++) {
            const int k0 = np * 128 + kc2 * 32;
            __syncthreads();
            if (tid < 256) {
                int v = tid & 127; int r = v >> 3; int c4 = (v & 7) * 4;
                int rr = r0 + r, bi = rr >> 3;
                const float* hs = (tid < 128) ? g_Hh : g_Hhpos;
                float4 h4 = *(const float4*)&hs[hb + (size_t)bi * HDIM + k0 + c4];
                const float* hz = &sh[HZB + kc2 * 576 + r * 36 + c4];
                float* d = sh + ((tid < 128) ? SAP : SAQ) + r * 36 + c4;
                d[0] = UF(f2tf(fmaxf(h4.x + hz[0], 0.f)));
                d[1] = UF(f2tf(fmaxf(h4.y + hz[1], 0.f)));
                d[2] = UF(f2tf(fmaxf(h4.z + hz[2], 0.f)));
                d[3] = UF(f2tf(fmaxf(h4.w + hz[3], 0.f)));
            }
            #pragma unroll
            for (int l = 0; l < 2; l++) {
                int v = tid + l * 512; int r = v >> 5; int c4 = (v & 31) * 4;
                *(uint4*)&sh[BBF + r * 136 + c4] =
                    *(const uint4*)&g_Wd2t[(size_t)(k0 + r) * ZDIM + c4];
            }
            __syncthreads();
            const float* pA = sh + (isp ? SAP : SAQ) + gg * 36 + tig;
            const float* pB = sh + BBF + tig * 136 + n0 + gg;
            #pragma unroll
            for (int kk = 0; kk < 4; kk++) {
                unsigned a[4] = { FU(pA[kk*8]), FU(pA[kk*8 + 288]),
                                  FU(pA[kk*8 + 4]), FU(pA[kk*8 + 292]) };
                mma8(acc0, a, FU(pB[kk*8*136]),     FU(pB[(kk*8 + 4)*136]));
                mma8(acc1, a, FU(pB[kk*8*136 + 8]), FU(pB[(kk*8 + 4)*136 + 8]));
            }
        }
    }

    // ---- epilogue ----
    __syncthreads();
    if (!isp) {   // q warps export fragments to QX (reuses B region)
        #pragma unroll
        for (int nt = 0; nt < 2; nt++) {
            const float* an = nt ? acc1 : acc0;
            int cb = n0 + nt * 8 + 2 * tig;
            *(float2*)&sh[QX + gg * 132 + cb]       = make_float2(an[0], an[1]);
            *(float2*)&sh[QX + (gg + 8) * 132 + cb] = make_float2(an[2], an[3]);
        }
    }
    __syncthreads();
    // back-pressure: p must have consumed z(t) before we overwrite g_z
    if (tid == 0) {
        while (((volatile int*)g_ack)[gidx] < t) __nanosleep(32);
    }
    __syncthreads();
    float kl = 0.f;
    if (isp) {
        #pragma unroll
        for (int nt = 0; nt < 2; nt++) {
            const float* an = nt ? acc1 : acc0;
            int cb = n0 + nt * 8 + 2 * tig;
            float2 bia = *(const float2*)&bd2[cb];
            #pragma unroll
            for (int rh = 0; rh < 2; rh++) {
                int row = r0 + gg + rh * 8;
                int bi = row >> 3, si = row & 7;
                float2 qv = *(float2*)&sh[QX + (gg + rh * 8) * 132 + cb];
                float pr0 = 0.1f * tanhf(an[rh*2]     + bia.x);
                float pr1 = 0.1f * tanhf(an[rh*2 + 1] + bia.y);
                float po0 = 0.1f * tanhf(qv.x + bia.x);
                float po1 = 0.1f * tanhf(qv.y + bia.y);
                float2 dv = *(const float2*)&g_diff[((size_t)t * BATCH + bi) * ZDIM + cb];
                float2 ev = *(const float2*)&noise[(((size_t)t * BATCH + bi) * SAMP + si) * ZDIM + cb];
                int zi = nt * 4 + rh * 2;
                zr[zi]     += DT * po0 + SQRT_DT * dv.x * ev.x;
                zr[zi + 1] += DT * po1 + SQRT_DT * dv.y * ev.y;
                __stcg((float2*)&g_z[(size_t)row * ZDIM + cb],
                       make_float2(zr[zi], zr[zi + 1]));
                int zb = ZB + (cb >> 5) * 576 + (gg + rh * 8) * 36 + (cb & 31);
                sh[zb]     = UF(f2tf(zr[zi]));
                sh[zb + 1] = UF(f2tf(zr[zi + 1]));
                float e0 = (pr0 - po0) / dv.x;
                float e1 = (pr1 - po1) / dv.y;
                kl += e0 * e0 + e1 * e1;
            }
        }
        __threadfence();   // make z(t+1) L2-visible before flag
    }
    __syncthreads();
    if (tid == 0) ((volatile int*)g_flag)[gidx] = t + 1;
    float* red = sh + REDO;
    red[tid] = kl;
    __syncthreads();
    for (int s = 256; s > 0; s >>= 1) {
        if (tid < s) red[tid] += red[tid + s];
        __syncthreads();
    }
    if (tid == 0) g_kldpart[t * 64 + gidx] = red[0];
    __syncthreads();
}

__device__ void p_step(int t, const float* __restrict__ bp2,
                       const float* __restrict__ X, float* sh, int gidx)
{
    const int tid = threadIdx.x;
    const int w = tid >> 5, lane = tid & 31, gg = lane >> 2, tig = lane & 3;
    const int r0 = gidx * 16;
    const size_t hb = (size_t)t * BATCH * HDIM;

    // wait for z(t+1), load into ZB (tf32 chunked)
    if (tid == 0) {
        while (((volatile int*)g_flag)[gidx] < t + 1) __nanosleep(32);
        __threadfence();
    }
    __syncthreads();
    {
        int e = tid * 4; int r = e >> 7; int c = e & 127;
        float4 z4 = ldcg4(&g_z[(size_t)(r0 + r) * ZDIM + c]);
        int base = ZB + (c >> 5) * 576 + r * 36 + (c & 31);
        sh[base]     = UF(f2tf(z4.x));
        sh[base + 1] = UF(f2tf(z4.y));
        sh[base + 2] = UF(f2tf(z4.z));
        sh[base + 3] = UF(f2tf(z4.w));
    }
    __syncthreads();
    if (tid == 0) {
        __threadfence();
        ((volatile int*)g_ack)[gidx] = t + 1;
    }

    float acc[4] = {0.f,0.f,0.f,0.f};   // p-head accum, n-tile = w*8
    for (int np = 0; np < 4; np++) {
        // ---- Hpz pass ----
        float ah[4] = {0.f,0.f,0.f,0.f};
        for (int kc = 0; kc < 4; kc++) {
            __syncthreads();
            #pragma unroll
            for (int l = 0; l < 2; l++) {
                int v = tid + l * 512; int r = v >> 5; int c4 = (v & 31) * 4;
                *(uint4*)&sh[BBF + r * 136 + c4] =
                    *(const uint4*)&g_Wp1zt[(size_t)(kc * 32 + r) * HDIM + np * 128 + c4];
            }
            __syncthreads();
            const float* pA = sh + ZB + kc * 576 + gg * 36 + tig;
            const float* pB = sh + BBF + tig * 136 + w * 8 + gg;
            #pragma unroll
            for (int kk = 0; kk < 4; kk++) {
                unsigned a[4] = { FU(pA[kk*8]), FU(pA[kk*8 + 288]),
                                  FU(pA[kk*8 + 4]), FU(pA[kk*8 + 292]) };
                mma8(ah, a, FU(pB[kk*8*136]), FU(pB[(kk*8 + 4)*136]));
            }
        }
        {
            int cl = w * 8 + 2 * tig;
            int base = HZB + (cl >> 5) * 576 + gg * 36 + (cl & 31);
            sh[base]       = ah[0];
            sh[base + 1]   = ah[1];
            sh[base + 288] = ah[2];
            sh[base + 289] = ah[3];
        }
        // ---- p-head chunks ----
        for (int kc2 = 0; kc2 < 4; kc2++) {
            const int k0 = np * 128 + kc2 * 32;
            __syncthreads();
            if (tid < 128) {
                int r = tid >> 3; int c4 = (tid & 7) * 4;
                int rr = r0 + r, bi = rr >> 3;
                float4 h4 = *(const float4*)&g_Hph[hb + (size_t)bi * HDIM + k0 + c4];
                const float* hz = &sh[HZB + kc2 * 576 + r * 36 + c4];
                float* d = sh + SAP + r * 36 + c4;
                d[0] = UF(f2tf(fmaxf(h4.x + hz[0], 0.f)));
                d[1] = UF(f2tf(fmaxf(h4.y + hz[1], 0.f)));
                d[2] = UF(f2tf(fmaxf(h4.z + hz[2], 0.f)));
                d[3] = UF(f2tf(fmaxf(h4.w + hz[3], 0.f)));
            }
            #pragma unroll
            for (int l = 0; l < 2; l++) {
                int v = tid + l * 512; int r = v >> 5; int c4 = (v & 31) * 4;
                *(uint4*)&sh[BBF + r * 136 + c4] =
                    *(const uint4*)&g_Wp2t[(size_t)(k0 + r) * ZDIM + c4];
            }
            __syncthreads();
            const float* pA = sh + SAP + gg * 36 + tig;
            const float* pB = sh + BBF + tig * 136 + w * 8 + gg;
            #pragma unroll
            for (int kk = 0; kk < 4; kk++) {
                unsigned a[4] = { FU(pA[kk*8]), FU(pA[kk*8 + 288]),
                                  FU(pA[kk*8 + 4]), FU(pA[kk*8 + 292]) };
                mma8(acc, a, FU(pB[kk*8*136]), FU(pB[(kk*8 + 4)*136]));
            }
        }
    }

    // ---- NLL epilogue ----
    const int n0 = w * 8;
    __syncthreads();
    if (w >= 8) {   // logvar warps export (acc + bias) to LVO (reuses B region)
        int cb = (n0 - 64) + 2 * tig;
        float2 bia = *(const float2*)&bp2[n0 + 2 * tig];
        *(float2*)&sh[LVO + gg * 68 + cb]       = make_float2(acc[0] + bia.x, acc[1] + bia.y);
        *(float2*)&sh[LVO + (gg + 8) * 68 + cb] = make_float2(acc[2] + bia.x, acc[3] + bia.y);
    }
    __syncthreads();
    float local = 0.f;
    if (w < 8) {
        int mc = n0 + 2 * tig;
        float2 bia = *(const float2*)&bp2[mc];
        #pragma unroll
        for (int rh = 0; rh < 2; rh++) {
            int row = r0 + gg + rh * 8;
            int bi = row >> 3;
            float mt = g_Mt[t * BATCH + bi];
            float2 lv = *(float2*)&sh[LVO + (gg + rh * 8) * 68 + mc];
            float2 xv = *(const float2*)&X[((size_t)t * BATCH + bi) * DIN + mc];
            float m0 = acc[rh*2] + bia.x, m1 = acc[rh*2 + 1] + bia.y;
            float d0 = xv.x - m0, d1 = xv.y - m1;
            local += mt * 0.5f * (LOG_2PI + lv.x + d0 * d0 * expf(-lv.x));
            local += mt * 0.5f * (LOG_2PI + lv.y + d1 * d1 * expf(-lv.y));
        }
    }
    float* red = sh + REDO;
    red[tid] = local;
    __syncthreads();
    for (int s = 256; s > 0; s >>= 1) {
        if (tid < s) red[tid] += red[tid + s];
        __syncthreads();
    }
    if (tid == 0) g_reconpart[t * 64 + gidx] = red[0];
    __syncthreads();
}

__global__ void __launch_bounds__(NTHR, 1)
scan_pairs(const float* __restrict__ bd2, const float* __restrict__ noise,
           const float* __restrict__ bp2, const float* __restrict__ X)
{
    __shared__ float sh[SH_TOT];   // 40.4 KB
    const int role = blockIdx.x & 1;
    const int gidx = blockIdx.x >> 1;
    const int tid = threadIdx.x;
    const int w = tid >> 5, lane = tid & 31, gg = lane >> 2, tig = lane & 3;
    const int r0 = gidx * 16;

    if (role == 0) {
        // init: z(0) -> zbuf (tf32) + zr regs (fp32, p-warps)
        {
            int e = tid * 4; int r = e >> 7; int c = e & 127;
            float4 z4 = ldcg4(&g_z[(size_t)(r0 + r) * ZDIM + c]);
            int base = ZB + (c >> 5) * 576 + r * 36 + (c & 31);
            sh[base]     = UF(f2tf(z4.x));
            sh[base + 1] = UF(f2tf(z4.y));
            sh[base + 2] = UF(f2tf(z4.z));
            sh[base + 3] = UF(f2tf(z4.w));
        }
        float zr[8];
        if (w < 8) {
            #pragma unroll
            for (int nt = 0; nt < 2; nt++)
                #pragma unroll
                for (int rh = 0; rh < 2; rh++) {
                    float2 z2 = ldcg2(&g_z[(size_t)(r0 + gg + rh * 8) * ZDIM
                                           + w * 16 + nt * 8 + 2 * tig]);
                    zr[nt * 4 + rh * 2]     = z2.x;
                    zr[nt * 4 + rh * 2 + 1] = z2.y;
                }
        }
        __syncthreads();
        for (int t = 0; t < T_STEPS; t++)
            drift_step(t, bd2, noise, sh, zr, gidx);
    } else {
        for (int t = 0; t < T_STEPS; t++)
            p_step(t, bp2, X, sh, gidx);
    }
}

// ---------------- outputs ---------------------------------------------------
__global__ void copy_z(float* __restrict__ out)
{
    int i = blockIdx.x * blockDim.x + threadIdx.x;
    out[i] = g_z[i];
}

__global__ void finalize(float* __restrict__ out, int out_size)
{
    int tid = threadIdx.x;   // 256
    if (tid < 64) { g_flag[tid] = 0; g_ack[tid] = 0; }   // reset for graph replay
    float k = 0.f, r = 0.f;
    for (int i = tid; i < T_STEPS * 64; i += 256) k += g_kldpart[i];
    for (int i = tid; i < T_STEPS * 64; i += 256) r += g_reconpart[i];
    __shared__ float rk[256], rr[256];
    rk[tid] = k; rr[tid] = r;
    __syncthreads();
    for (int s = 128; s > 0; s >>= 1) {
        if (tid < s) { rk[tid] += rk[tid + s]; rr[tid] += rr[tid + s]; }
        __syncthreads();
    }
    if (tid == 0) {
        float kld   = rk[0] * (0.5f * DT / (float)BS);
        float recon = rr[0] * (1.f / (float)BS);
        out[out_size - 3] = recon + kld;
        out[out_size - 2] = recon;
        out[out_size - 1] = kld;
    }
}

// ---------------- launch ----------------------------------------------------
extern "C" void kernel_launch(void* const* d_in, const int* in_sizes, int n_in,
                              void* d_out, int out_size)
{
    const float* X     = (const float*)d_in[0];
    const float* M     = (const float*)d_in[1];
    const float* cov   = (const float*)d_in[2];
    const float* ph    = (const float*)d_in[3];
    const float* phpos = (const float*)d_in[4];
    const float* noise = (const float*)d_in[5];
    const float* Wc1 = (const float*)d_in[6],  *bc1 = (const float*)d_in[7];
    const float* Wc2 = (const float*)d_in[8],  *bc2 = (const float*)d_in[9];
    const float* Wd1 = (const float*)d_in[10], *bd1 = (const float*)d_in[11];
    const float* Wd2 = (const float*)d_in[12], *bd2 = (const float*)d_in[13];
    const float* Wf1 = (const float*)d_in[14], *bf1 = (const float*)d_in[15];
    const float* Wf2 = (const float*)d_in[16], *bf2 = (const float*)d_in[17];
    const float* Wp1 = (const float*)d_in[18], *bp1 = (const float*)d_in[19];
    const float* Wp2 = (const float*)d_in[20], *bp2 = (const float*)d_in[21];
    float* out = (float*)d_out;

    float *pHh, *pHhpos, *pHph, *pHf, *pdiff;
    cudaGetSymbolAddress((void**)&pHh,    g_Hh);
    cudaGetSymbolAddress((void**)&pHhpos, g_Hhpos);
    cudaGetSymbolAddress((void**)&pHph,   g_Hph);
    cudaGetSymbolAddress((void**)&pHf,    g_Hf);
    cudaGetSymbolAddress((void**)&pdiff,  g_diff);

    // ---- precompute (parallel over all T) ----
    z0_kernel<<<BATCH, 128>>>(cov, Wc1, bc1, Wc2, bc2);
    mt_kernel<<<64, 256>>>(M);
    cvt_weights<<<256, 256>>>(Wd2, Wp1, Wd1, Wp2);
    gemm_f32<0, false><<<dim3(HDIM/64, TB/64), 256>>>(ph,  nullptr, Wd1, bd1, pHh,    TB, HDIM, RDIM);
    gemm_f32<0, true ><<<dim3(HDIM/64, TB/64), 256>>>(ph,  phpos,   Wd1, bd1, pHhpos, TB, HDIM, RDIM);
    gemm_f32<0, false><<<dim3(HDIM/64, TB/64), 256>>>(ph,  nullptr, Wp1, bp1, pHph,   TB, HDIM, RDIM);
    gemm_f32<1, false><<<dim3(HDIM/64, TB/64), 256>>>(ph,  nullptr, Wf1, bf1, pHf,    TB, HDIM, RDIM);
    gemm_f32<2, false><<<dim3(ZDIM/64, TB/64), 256>>>(pHf, nullptr, Wf2, bf2, pdiff,  TB, ZDIM, HDIM);

    // ---- barrier-free pairwise scan ----
    scan_pairs<<<128, NTHR>>>(bd2, noise, bp2, X);

    // ---- outputs ----
    copy_z<<<(BS * ZDIM) / 256, 256>>>(out);
    finalize<<<1, 256>>>(out, out_size);
}

// round 7
// speedup vs baseline: 2.3932x; 2.3932x over previous
#include <cuda_runtime.h>
#include <math.h>
#include <stdint.h>

#define T_STEPS 128
#define BATCH   128
#define SAMP    8
#define DIN     64
#define RDIM    256
#define ZDIM    128
#define HDIM    512
#define BS      1024
#define TB      16384
#define NTHR    512

#define DT       0.05f
#define SQRT_DT  0.22360679774997896f
#define LOG_2PI  1.8378770664093453f

// ---------------- scratch ---------------------------------------------------
__device__ __align__(16) float g_Hh[TB * HDIM];
__device__ __align__(16) float g_Hhpos[TB * HDIM];
__device__ __align__(16) float g_Hph[TB * HDIM];
__device__ __align__(16) float g_Hf[TB * HDIM];
__device__ __align__(16) float g_diff[TB * ZDIM];
__device__ __align__(16) float g_Mt[T_STEPS * BATCH];
__device__ __align__(16) float g_z[BS * ZDIM];
// bf16 transposed weights: WT[n][k] packed pairs (k even lo, k odd hi)
__device__ __align__(16) unsigned g_Wd1zT[HDIM * ZDIM / 2];  // [512][64]
__device__ __align__(16) unsigned g_Wd2T[ZDIM * HDIM / 2];   // [128][256]
__device__ __align__(16) unsigned g_Wp1zT[HDIM * ZDIM / 2];  // [512][64]
__device__ __align__(16) unsigned g_Wp2T[ZDIM * HDIM / 2];   // [128][256]
__device__ float g_kldpart[T_STEPS * 64];
__device__ float g_reconpart[T_STEPS * 64];
__device__ int g_flag[64];
__device__ int g_ack[64];

__device__ __forceinline__ float4 ldcg4(const float* p) { return __ldcg((const float4*)p); }
__device__ __forceinline__ float2 ldcg2(const float* p) { return __ldcg((const float2*)p); }
__device__ __forceinline__ unsigned f2tf(float f) {
    unsigned r; asm("cvt.rna.tf32.f32 %0, %1;" : "=r"(r) : "f"(f)); return r;
}
__device__ __forceinline__ unsigned packbf(float lo, float hi) {
    unsigned r; asm("cvt.rn.bf16x2.f32 %0, %1, %2;" : "=r"(r) : "f"(hi), "f"(lo)); return r;
}
#define FU(x)  __float_as_uint(x)
#define UF(x)  __uint_as_float(x)

__device__ __forceinline__ void mma8(float c[4], const unsigned a[4],
                                     unsigned b0, unsigned b1)
{
    asm volatile(
        "mma.sync.aligned.m16n8k8.row.col.f32.tf32.tf32.f32 "
        "{%0,%1,%2,%3}, {%4,%5,%6,%7}, {%8,%9}, {%0,%1,%2,%3};"
        : "+f"(c[0]), "+f"(c[1]), "+f"(c[2]), "+f"(c[3])
        : "r"(a[0]), "r"(a[1]), "r"(a[2]), "r"(a[3]), "r"(b0), "r"(b1));
}
__device__ __forceinline__ void mma16(float c[4], const unsigned a[4],
                                      unsigned b0, unsigned b1)
{
    asm volatile(
        "mma.sync.aligned.m16n8k16.row.col.f32.bf16.bf16.f32 "
        "{%0,%1,%2,%3}, {%4,%5,%6,%7}, {%8,%9}, {%0,%1,%2,%3};"
        : "+f"(c[0]), "+f"(c[1]), "+f"(c[2]), "+f"(c[3])
        : "r"(a[0]), "r"(a[1]), "r"(a[2]), "r"(a[3]), "r"(b0), "r"(b1));
}

// ---------------- z0 --------------------------------------------------------
__global__ void z0_kernel(const float* __restrict__ cov,
                          const float* __restrict__ Wc1, const float* __restrict__ bc1,
                          const float* __restrict__ Wc2, const float* __restrict__ bc2)
{
    int b = blockIdx.x;
    int tid = threadIdx.x;  // 128
    __shared__ float sc[32];
    __shared__ float shh[64];
    if (tid < 32) sc[tid] = cov[b * 32 + tid];
    __syncthreads();
    if (tid < 64) {
        float acc = bc1[tid];
        #pragma unroll
        for (int c = 0; c < 32; c++) acc = fmaf(sc[c], Wc1[c * 64 + tid], acc);
        shh[tid] = fmaxf(acc, 0.f);
    }
    __syncthreads();
    float acc = bc2[tid];
    #pragma unroll
    for (int k = 0; k < 64; k++) acc = fmaf(shh[k], Wc2[k * 128 + tid], acc);
    float z = tanhf(acc);
    #pragma unroll
    for (int s = 0; s < SAMP; s++)
        g_z[(b * SAMP + s) * ZDIM + tid] = z;
}

// ---------------- Mt --------------------------------------------------------
__global__ void mt_kernel(const float* __restrict__ M)
{
    int i = blockIdx.x * blockDim.x + threadIdx.x;
    const float4* p = (const float4*)(M + (size_t)i * DIN);
    float s = 0.f;
    #pragma unroll
    for (int j = 0; j < DIN / 4; j++) { float4 v = p[j]; s += v.x + v.y + v.z + v.w; }
    g_Mt[i] = s * (1.f / (float)DIN);
}

// ---------------- weight transpose + bf16 pack ------------------------------
// W fp32 [K][N] -> WT packed bf16 [N][K/2]
__global__ void transpose_bf16(const float* __restrict__ W, unsigned* __restrict__ WT,
                               int K, int N)
{
    int n  = blockIdx.x * 32 + (threadIdx.x & 31);
    int kp = blockIdx.y * 8 + (threadIdx.x >> 5);
    if (n < N && kp < K / 2) {
        float lo = W[(size_t)(2 * kp) * N + n];
        float hi = W[(size_t)(2 * kp + 1) * N + n];
        WT[(size_t)n * (K / 2) + kp] = packbf(lo, hi);
    }
}

// ---------------- tf32 MMA precompute GEMM ----------------------------------
// C[M,N] = act(A@W + bias). Tiles 64x128, 512 threads, on-the-fly tf32 cvt.
template<int ACT, bool SUMA>
__global__ void __launch_bounds__(512, 2)
gemm_tf32(const float* __restrict__ A, const float* __restrict__ A2,
          const float* __restrict__ W, const float* __restrict__ bias,
          float* __restrict__ C, int M, int N, int K)
{
    __shared__ float sA[64 * 36];
    __shared__ float sB[32 * 136];
    const int tid = threadIdx.x;
    const int w = tid >> 5, lane = tid & 31, g = lane >> 2, tig = lane & 3;
    const int bm = blockIdx.y * 64, bn = blockIdx.x * 128;
    const int mt = w & 3, n0 = (w >> 2) * 32;
    float acc[4][4] = {};
    for (int k0 = 0; k0 < K; k0 += 32) {
        __syncthreads();
        {
            int r = tid >> 3, c4 = (tid & 7) * 4;
            float4 av = *(const float4*)&A[(size_t)(bm + r) * K + k0 + c4];
            if (SUMA) {
                float4 b4 = *(const float4*)&A2[(size_t)(bm + r) * K + k0 + c4];
                av.x += b4.x; av.y += b4.y; av.z += b4.z; av.w += b4.w;
            }
            float* d = &sA[r * 36 + c4];
            d[0] = UF(f2tf(av.x)); d[1] = UF(f2tf(av.y));
            d[2] = UF(f2tf(av.z)); d[3] = UF(f2tf(av.w));
        }
        #pragma unroll
        for (int l = 0; l < 2; l++) {
            int v = tid + l * 512;
            int r = v >> 5, c4 = (v & 31) * 4;
            float4 wv = *(const float4*)&W[(size_t)(k0 + r) * N + bn + c4];
            float* d = &sB[r * 136 + c4];
            d[0] = UF(f2tf(wv.x)); d[1] = UF(f2tf(wv.y));
            d[2] = UF(f2tf(wv.z)); d[3] = UF(f2tf(wv.w));
        }
        __syncthreads();
        const float* pA = sA + (mt * 16 + g) * 36 + tig;
        const float* pB = sB + tig * 136 + n0 + g;
        #pragma unroll
        for (int kk = 0; kk < 4; kk++) {
            unsigned a[4] = { FU(pA[kk*8]), FU(pA[kk*8 + 288]),
                              FU(pA[kk*8 + 4]), FU(pA[kk*8 + 292]) };
            #pragma unroll
            for (int nt = 0; nt < 4; nt++) {
                unsigned b0 = FU(pB[kk*8*136 + nt*8]);
                unsigned b1 = FU(pB[(kk*8 + 4)*136 + nt*8]);
                mma8(acc[nt], a, b0, b1);
            }
        }
    }
    #pragma unroll
    for (int nt = 0; nt < 4; nt++) {
        int cb = bn + n0 + nt * 8 + 2 * tig;
        float b0 = bias[cb], b1 = bias[cb + 1];
        #pragma unroll
        for (int rh = 0; rh < 2; rh++) {
            int row = bm + mt * 16 + g + rh * 8;
            float v0 = acc[nt][rh*2] + b0, v1 = acc[nt][rh*2 + 1] + b1;
            if (ACT == 1) { v0 = fmaxf(v0, 0.f); v1 = fmaxf(v1, 0.f); }
            if (ACT == 2) { v0 = expf(v0); v1 = expf(v1); }
            *(float2*)&C[(size_t)row * N + cb] = make_float2(v0, v1);
        }
    }
}

// ================= bf16 pairwise scan ========================================
// Block 2g: drift (z resident). Block 2g+1: p-head/NLL. 16 rows per pair.

// smem layout (float/uint units)
#define ZB    0        /* z bf16 packed [16][68]       */
#define SAP   1088     /* A_p bf16 [16][68]            */
#define SAQ   2176     /* A_q bf16 [16][68] / LVO fp32 */
#define HZB   3264     /* Hz fp32 [16][132]            */
#define BB    5376     /* B bf16 [128][36]             */
#define RED   9984     /* [32]                         */
#define SH_TOT 10016
#define LVO   SAQ

__device__ __forceinline__ void pf_ld(const unsigned* base, int stride, int tid,
                                      uint4& b0, uint4& b1)
{
    b0 = *(const uint4*)(base + (size_t)(tid >> 3) * stride + (tid & 7) * 4);
    b1 = *(const uint4*)(base + (size_t)((tid + 512) >> 3) * stride + ((tid + 512) & 7) * 4);
}
__device__ __forceinline__ void pf_st(unsigned* shu, int tid, uint4 b0, uint4 b1)
{
    *(uint4*)&shu[BB + (tid >> 3) * 36 + (tid & 7) * 4] = b0;
    *(uint4*)&shu[BB + ((tid + 512) >> 3) * 36 + ((tid + 512) & 7) * 4] = b1;
}
__device__ __forceinline__ const unsigned* bsrc(const unsigned* W1T, const unsigned* W2T,
                                                int np, int st, int& stride)
{
    if (st < 2) { stride = 64;  return W1T + (size_t)(np * 128) * 64 + st * 32; }
    else        { stride = 256; return W2T + (size_t)np * 64 + (st - 2) * 32; }
}

// preload z fragments (8 k16-groups x 4 regs) from ZB
__device__ __forceinline__ void load_za(const unsigned* shu, int g, int tig,
                                        unsigned za[8][4])
{
    const unsigned* pz = shu + ZB + g * 68 + tig;
    #pragma unroll
    for (int kk = 0; kk < 8; kk++) {
        za[kk][0] = pz[kk*8];
        za[kk][1] = pz[kk*8 + 544];
        za[kk][2] = pz[kk*8 + 4];
        za[kk][3] = pz[kk*8 + 548];
    }
}

__device__ void drift_step(int t, const float* __restrict__ bd2,
                           const float* __restrict__ noise,
                           float* sh, float zr[4], int gidx)
{
    unsigned* shu = (unsigned*)sh;
    const int tid = threadIdx.x;
    const int w = tid >> 5, lane = tid & 31, g = lane >> 2, tig = lane & 3;
    const int r0 = gidx * 16;
    const size_t hb = (size_t)t * BATCH * HDIM;

    uint4 br0, br1;
    { int stride; const unsigned* s = bsrc(g_Wd1zT, g_Wd2T, 0, 0, stride);
      pf_ld(s, stride, tid, br0, br1); }

    unsigned za[8][4];
    load_za(shu, g, tig, za);

    float accp[4] = {0.f,0.f,0.f,0.f}, accq[4] = {0.f,0.f,0.f,0.f};

    for (int np = 0; np < 4; np++) {
        float ahz[4] = {0.f,0.f,0.f,0.f};
        for (int st = 0; st < 4; st++) {
            __syncthreads();                   // BB free
            pf_st(shu, tid, br0, br1);
            __syncthreads();                   // BB ready
            {   // prefetch next stage (LDG in flight during MMA)
                int nl = np * 4 + st + 1;
                if (nl < 16) {
                    int stride;
                    const unsigned* s = bsrc(g_Wd1zT, g_Wd2T, nl >> 2, nl & 3, stride);
                    pf_ld(s, stride, tid, br0, br1);
                }
            }
            if (st < 2) {
                const unsigned* pB = shu + BB + (w * 8 + g) * 36 + tig;
                #pragma unroll
                for (int kk = 0; kk < 4; kk++)
                    mma16(ahz, za[st * 4 + kk], pB[kk*8], pB[kk*8 + 4]);
                if (st == 1) {
                    int cb = w * 8 + 2 * tig;
                    *(float2*)&sh[HZB + g * 132 + cb]       = make_float2(ahz[0], ahz[1]);
                    *(float2*)&sh[HZB + (g + 8) * 132 + cb] = make_float2(ahz[2], ahz[3]);
                    __syncthreads();           // HZB visible
                    #pragma unroll
                    for (int l = 0; l < 2; l++) {   // A staging: relu(Hh/Hhpos + Hz) bf16
                        int v = tid + l * 512;
                        int arr = v >> 9, idx = v & 511;
                        int r = idx >> 5, c4 = (idx & 31) * 4;
                        int bi = (r0 + r) >> 3;
                        const float* hs = arr ? g_Hhpos : g_Hh;
                        float4 h4 = *(const float4*)&hs[hb + (size_t)bi * HDIM + np * 128 + c4];
                        float4 z4 = *(const float4*)&sh[HZB + r * 132 + c4];
                        unsigned u0 = packbf(fmaxf(h4.x + z4.x, 0.f), fmaxf(h4.y + z4.y, 0.f));
                        unsigned u1 = packbf(fmaxf(h4.z + z4.z, 0.f), fmaxf(h4.w + z4.w, 0.f));
                        *(uint2*)&shu[(arr ? SAQ : SAP) + r * 68 + (c4 >> 1)] = make_uint2(u0, u1);
                    }
                }
            } else {
                const unsigned* pAp = shu + SAP + g * 68 + (st - 2) * 32 + tig;
                const unsigned* pAq = shu + SAQ + g * 68 + (st - 2) * 32 + tig;
                const unsigned* pB  = shu + BB + (w * 8 + g) * 36 + tig;
                #pragma unroll
                for (int kk = 0; kk < 4; kk++) {
                    unsigned ap[4] = { pAp[kk*8], pAp[kk*8 + 544], pAp[kk*8 + 4], pAp[kk*8 + 548] };
                    unsigned aq[4] = { pAq[kk*8], pAq[kk*8 + 544], pAq[kk*8 + 4], pAq[kk*8 + 548] };
                    unsigned b0 = pB[kk*8], b1 = pB[kk*8 + 4];
                    mma16(accp, ap, b0, b1);
                    mma16(accq, aq, b0, b1);
                }
            }
        }
    }

    // ---- epilogue: prior/poster on fragments, z update, KLD ----
    if (tid == 0) {
        while (((volatile int*)g_ack)[gidx] < t) __nanosleep(64);
    }
    __syncthreads();
    const int c = w * 8 + 2 * tig;
    float2 bia = *(const float2*)&bd2[c];
    float kl = 0.f;
    #pragma unroll
    for (int rh = 0; rh < 2; rh++) {
        int row = r0 + g + rh * 8;
        int bi = row >> 3, si = row & 7;
        float2 dv = *(const float2*)&g_diff[((size_t)t * BATCH + bi) * ZDIM + c];
        float2 ev = *(const float2*)&noise[(((size_t)t * BATCH + bi) * SAMP + si) * ZDIM + c];
        float pr0 = 0.1f * tanhf(accp[rh*2]     + bia.x);
        float pr1 = 0.1f * tanhf(accp[rh*2 + 1] + bia.y);
        float po0 = 0.1f * tanhf(accq[rh*2]     + bia.x);
        float po1 = 0.1f * tanhf(accq[rh*2 + 1] + bia.y);
        zr[rh*2]     += DT * po0 + SQRT_DT * dv.x * ev.x;
        zr[rh*2 + 1] += DT * po1 + SQRT_DT * dv.y * ev.y;
        __stcg((float2*)&g_z[(size_t)row * ZDIM + c], make_float2(zr[rh*2], zr[rh*2 + 1]));
        shu[ZB + (g + rh * 8) * 68 + (c >> 1)] = packbf(zr[rh*2], zr[rh*2 + 1]);
        float e0 = (pr0 - po0) / dv.x;
        float e1 = (pr1 - po1) / dv.y;
        kl += e0 * e0 + e1 * e1;
    }
    __threadfence();
    __syncthreads();
    if (tid == 0) ((volatile int*)g_flag)[gidx] = t + 1;
    #pragma unroll
    for (int o = 16; o > 0; o >>= 1) kl += __shfl_xor_sync(~0u, kl, o);
    if (lane == 0) sh[RED + w] = kl;
    __syncthreads();
    if (tid < 32) {
        float v = (tid < 16) ? sh[RED + tid] : 0.f;
        #pragma unroll
        for (int o = 8; o > 0; o >>= 1) v += __shfl_xor_sync(~0u, v, o);
        if (tid == 0) g_kldpart[t * 64 + gidx] = v;
    }
    __syncthreads();
}

__device__ void p_step(int t, const float* __restrict__ bp2,
                       const float* __restrict__ X, float* sh, int gidx)
{
    unsigned* shu = (unsigned*)sh;
    const int tid = threadIdx.x;
    const int w = tid >> 5, lane = tid & 31, g = lane >> 2, tig = lane & 3;
    const int r0 = gidx * 16;
    const size_t hb = (size_t)t * BATCH * HDIM;

    uint4 br0, br1;
    { int stride; const unsigned* s = bsrc(g_Wp1zT, g_Wp2T, 0, 0, stride);
      pf_ld(s, stride, tid, br0, br1); }

    // wait for z(t+1), stage to ZB bf16
    if (tid == 0) {
        while (((volatile int*)g_flag)[gidx] < t + 1) __nanosleep(64);
        __threadfence();
    }
    __syncthreads();
    {
        int r = tid >> 5, c4 = (tid & 31) * 4;
        float4 z4 = ldcg4(&g_z[(size_t)(r0 + r) * ZDIM + c4]);
        shu[ZB + r * 68 + (c4 >> 1)]     = packbf(z4.x, z4.y);
        shu[ZB + r * 68 + (c4 >> 1) + 1] = packbf(z4.z, z4.w);
    }
    __syncthreads();
    if (tid == 0) {
        __threadfence();
        ((volatile int*)g_ack)[gidx] = t + 1;
    }

    unsigned za[8][4];
    load_za(shu, g, tig, za);

    float acc[4] = {0.f,0.f,0.f,0.f};
    for (int np = 0; np < 4; np++) {
        float ahz[4] = {0.f,0.f,0.f,0.f};
        for (int st = 0; st < 4; st++) {
            __syncthreads();
            pf_st(shu, tid, br0, br1);
            __syncthreads();
            {
                int nl = np * 4 + st + 1;
                if (nl < 16) {
                    int stride;
                    const unsigned* s = bsrc(g_Wp1zT, g_Wp2T, nl >> 2, nl & 3, stride);
                    pf_ld(s, stride, tid, br0, br1);
                }
            }
            if (st < 2) {
                const unsigned* pB = shu + BB + (w * 8 + g) * 36 + tig;
                #pragma unroll
                for (int kk = 0; kk < 4; kk++)
                    mma16(ahz, za[st * 4 + kk], pB[kk*8], pB[kk*8 + 4]);
                if (st == 1) {
                    int cb = w * 8 + 2 * tig;
                    *(float2*)&sh[HZB + g * 132 + cb]       = make_float2(ahz[0], ahz[1]);
                    *(float2*)&sh[HZB + (g + 8) * 132 + cb] = make_float2(ahz[2], ahz[3]);
                    __syncthreads();
                    {   // A staging: relu(Hph + Hpz) bf16 (single tile)
                        int r = tid >> 5, c4 = (tid & 31) * 4;
                        int bi = (r0 + r) >> 3;
                        float4 h4 = *(const float4*)&g_Hph[hb + (size_t)bi * HDIM + np * 128 + c4];
                        float4 z4 = *(const float4*)&sh[HZB + r * 132 + c4];
                        unsigned u0 = packbf(fmaxf(h4.x + z4.x, 0.f), fmaxf(h4.y + z4.y, 0.f));
                        unsigned u1 = packbf(fmaxf(h4.z + z4.z, 0.f), fmaxf(h4.w + z4.w, 0.f));
                        *(uint2*)&shu[SAP + r * 68 + (c4 >> 1)] = make_uint2(u0, u1);
                    }
                }
            } else {
                const unsigned* pAp = shu + SAP + g * 68 + (st - 2) * 32 + tig;
                const unsigned* pB  = shu + BB + (w * 8 + g) * 36 + tig;
                #pragma unroll
                for (int kk = 0; kk < 4; kk++) {
                    unsigned ap[4] = { pAp[kk*8], pAp[kk*8 + 544], pAp[kk*8 + 4], pAp[kk*8 + 548] };
                    mma16(acc, ap, pB[kk*8], pB[kk*8 + 4]);
                }
            }
        }
    }

    // ---- NLL epilogue ----
    __syncthreads();
    if (w >= 8) {   // logvar warps: export acc+bias (cols 64..127)
        int cb = (w - 8) * 8 + 2 * tig;
        float2 bia = *(const float2*)&bp2[64 + cb];
        *(float2*)&sh[LVO + g * 68 + cb]       = make_float2(acc[0] + bia.x, acc[1] + bia.y);
        *(float2*)&sh[LVO + (g + 8) * 68 + cb] = make_float2(acc[2] + bia.x, acc[3] + bia.y);
    }
    __syncthreads();
    float local = 0.f;
    if (w < 8) {
        int mc = w * 8 + 2 * tig;
        float2 bia = *(const float2*)&bp2[mc];
        #pragma unroll
        for (int rh = 0; rh < 2; rh++) {
            int row = r0 + g + rh * 8;
            int bi = row >> 3;
            float mt = g_Mt[t * BATCH + bi];
            float2 lv = *(float2*)&sh[LVO + (g + rh * 8) * 68 + mc];
            float2 xv = *(const float2*)&X[((size_t)t * BATCH + bi) * DIN + mc];
            float m0 = acc[rh*2] + bia.x, m1 = acc[rh*2 + 1] + bia.y;
            float d0 = xv.x - m0, d1 = xv.y - m1;
            local += mt * 0.5f * (LOG_2PI + lv.x + d0 * d0 * expf(-lv.x));
            local += mt * 0.5f * (LOG_2PI + lv.y + d1 * d1 * expf(-lv.y));
        }
    }
    #pragma unroll
    for (int o = 16; o > 0; o >>= 1) local += __shfl_xor_sync(~0u, local, o);
    if (lane == 0) sh[RED + w] = local;
    __syncthreads();
    if (tid < 32) {
        float v = (tid < 16) ? sh[RED + tid] : 0.f;
        #pragma unroll
        for (int o = 8; o > 0; o >>= 1) v += __shfl_xor_sync(~0u, v, o);
        if (tid == 0) g_reconpart[t * 64 + gidx] = v;
    }
    __syncthreads();
}

__global__ void __launch_bounds__(NTHR, 1)
scan_pairs(const float* __restrict__ bd2, const float* __restrict__ noise,
           const float* __restrict__ bp2, const float* __restrict__ X)
{
    __shared__ float sh[SH_TOT];
    unsigned* shu = (unsigned*)sh;
    const int role = blockIdx.x & 1;
    const int gidx = blockIdx.x >> 1;
    const int tid = threadIdx.x;
    const int w = tid >> 5, lane = tid & 31, g = lane >> 2, tig = lane & 3;
    const int r0 = gidx * 16;

    if (role == 0) {
        {   // init ZB (bf16) from z0
            int r = tid >> 5, c4 = (tid & 31) * 4;
            float4 z4 = ldcg4(&g_z[(size_t)(r0 + r) * ZDIM + c4]);
            shu[ZB + r * 68 + (c4 >> 1)]     = packbf(z4.x, z4.y);
            shu[ZB + r * 68 + (c4 >> 1) + 1] = packbf(z4.z, z4.w);
        }
        float zr[4];   // reg-resident z fragment (rows g,g+8; cols w*8+2tig,+1)
        {
            int c = w * 8 + 2 * tig;
            float2 a = ldcg2(&g_z[(size_t)(r0 + g) * ZDIM + c]);
            float2 b = ldcg2(&g_z[(size_t)(r0 + g + 8) * ZDIM + c]);
            zr[0] = a.x; zr[1] = a.y; zr[2] = b.x; zr[3] = b.y;
        }
        __syncthreads();
        for (int t = 0; t < T_STEPS; t++)
            drift_step(t, bd2, noise, sh, zr, gidx);
    } else {
        for (int t = 0; t < T_STEPS; t++)
            p_step(t, bp2, X, sh, gidx);
    }
}

// ---------------- outputs ---------------------------------------------------
__global__ void copy_z(float* __restrict__ out)
{
    int i = blockIdx.x * blockDim.x + threadIdx.x;
    out[i] = g_z[i];
}

__global__ void finalize(float* __restrict__ out, int out_size)
{
    int tid = threadIdx.x;   // 256
    if (tid < 64) { g_flag[tid] = 0; g_ack[tid] = 0; }   // reset for graph replay
    float k = 0.f, r = 0.f;
    for (int i = tid; i < T_STEPS * 64; i += 256) k += g_kldpart[i];
    for (int i = tid; i < T_STEPS * 64; i += 256) r += g_reconpart[i];
    __shared__ float rk[256], rr[256];
    rk[tid] = k; rr[tid] = r;
    __syncthreads();
    for (int s = 128; s > 0; s >>= 1) {
        if (tid < s) { rk[tid] += rk[tid + s]; rr[tid] += rr[tid + s]; }
        __syncthreads();
    }
    if (tid == 0) {
        float kld   = rk[0] * (0.5f * DT / (float)BS);
        float recon = rr[0] * (1.f / (float)BS);
        out[out_size - 3] = recon + kld;
        out[out_size - 2] = recon;
        out[out_size - 1] = kld;
    }
}

// ---------------- launch ----------------------------------------------------
extern "C" void kernel_launch(void* const* d_in, const int* in_sizes, int n_in,
                              void* d_out, int out_size)
{
    const float* X     = (const float*)d_in[0];
    const float* M     = (const float*)d_in[1];
    const float* cov   = (const float*)d_in[2];
    const float* ph    = (const float*)d_in[3];
    const float* phpos = (const float*)d_in[4];
    const float* noise = (const float*)d_in[5];
    const float* Wc1 = (const float*)d_in[6],  *bc1 = (const float*)d_in[7];
    const float* Wc2 = (const float*)d_in[8],  *bc2 = (const float*)d_in[9];
    const float* Wd1 = (const float*)d_in[10], *bd1 = (const float*)d_in[11];
    const float* Wd2 = (const float*)d_in[12], *bd2 = (const float*)d_in[13];
    const float* Wf1 = (const float*)d_in[14], *bf1 = (const float*)d_in[15];
    const float* Wf2 = (const float*)d_in[16], *bf2 = (const float*)d_in[17];
    const float* Wp1 = (const float*)d_in[18], *bp1 = (const float*)d_in[19];
    const float* Wp2 = (const float*)d_in[20], *bp2 = (const float*)d_in[21];
    float* out = (float*)d_out;

    float *pHh, *pHhpos, *pHph, *pHf, *pdiff;
    unsigned *pWd1zT, *pWd2T, *pWp1zT, *pWp2T;
    cudaGetSymbolAddress((void**)&pHh,    g_Hh);
    cudaGetSymbolAddress((void**)&pHhpos, g_Hhpos);
    cudaGetSymbolAddress((void**)&pHph,   g_Hph);
    cudaGetSymbolAddress((void**)&pHf,    g_Hf);
    cudaGetSymbolAddress((void**)&pdiff,  g_diff);
    cudaGetSymbolAddress((void**)&pWd1zT, g_Wd1zT);
    cudaGetSymbolAddress((void**)&pWd2T,  g_Wd2T);
    cudaGetSymbolAddress((void**)&pWp1zT, g_Wp1zT);
    cudaGetSymbolAddress((void**)&pWp2T,  g_Wp2T);

    // ---- precompute ----
    z0_kernel<<<BATCH, 128>>>(cov, Wc1, bc1, Wc2, bc2);
    mt_kernel<<<64, 256>>>(M);
    // weight transposes to bf16 [N][K/2]
    transpose_bf16<<<dim3(16, 8),  256>>>(Wd1 + RDIM * HDIM, pWd1zT, ZDIM, HDIM);
    transpose_bf16<<<dim3(4, 32),  256>>>(Wd2,               pWd2T,  HDIM, ZDIM);
    transpose_bf16<<<dim3(16, 8),  256>>>(Wp1 + RDIM * HDIM, pWp1zT, ZDIM, HDIM);
    transpose_bf16<<<dim3(4, 32),  256>>>(Wp2,               pWp2T,  HDIM, ZDIM);
    // big h-GEMMs (tf32 MMA)
    gemm_tf32<0, false><<<dim3(4, 256), 512>>>(ph,  nullptr, Wd1, bd1, pHh,    TB, HDIM, RDIM);
    gemm_tf32<0, true ><<<dim3(4, 256), 512>>>(ph,  phpos,   Wd1, bd1, pHhpos, TB, HDIM, RDIM);
    gemm_tf32<0, false><<<dim3(4, 256), 512>>>(ph,  nullptr, Wp1, bp1, pHph,   TB, HDIM, RDIM);
    gemm_tf32<1, false><<<dim3(4, 256), 512>>>(ph,  nullptr, Wf1, bf1, pHf,    TB, HDIM, RDIM);
    gemm_tf32<2, false><<<dim3(1, 256), 512>>>(pHf, nullptr, Wf2, bf2, pdiff,  TB, ZDIM, HDIM);

    // ---- bf16 pairwise scan ----
    scan_pairs<<<128, NTHR>>>(bd2, noise, bp2, X);

    // ---- outputs ----
    copy_z<<<(BS * ZDIM) / 256, 256>>>(out);
    finalize<<<1, 256>>>(out, out_size);
}

// round 8
// speedup vs baseline: 2.6900x; 1.1240x over previous
#include <cuda_runtime.h>
#include <math.h>
#include <stdint.h>

#define T_STEPS 128
#define BATCH   128
#define SAMP    8
#define DIN     64
#define RDIM    256
#define ZDIM    128
#define HDIM    512
#define BS      1024
#define TB      16384
#define NTHR    512

#define DT       0.05f
#define SQRT_DT  0.22360679774997896f
#define LOG_2PI  1.8378770664093453f

// ---------------- scratch ---------------------------------------------------
__device__ __align__(16) float g_Hh[TB * HDIM];
__device__ __align__(16) float g_Hhpos[TB * HDIM];
__device__ __align__(16) float g_Hph[TB * HDIM];
__device__ __align__(16) float g_Hf[TB * HDIM];
__device__ __align__(16) float g_diff[TB * ZDIM];
__device__ __align__(16) float g_Mt[T_STEPS * BATCH];
__device__ __align__(16) float g_z[BS * ZDIM];
// bf16 transposed weights: WT[n][k/2] packed pairs (k even lo, k odd hi)
__device__ __align__(16) unsigned g_Wd1zT[HDIM * ZDIM / 2];  // [512][64]
__device__ __align__(16) unsigned g_Wd2T[ZDIM * HDIM / 2];   // [128][256]
__device__ __align__(16) unsigned g_Wp1zT[HDIM * ZDIM / 2];  // [512][64]
__device__ __align__(16) unsigned g_Wp2T[ZDIM * HDIM / 2];   // [128][256]
__device__ float g_kldpart[T_STEPS * 64];
__device__ float g_reconpart[T_STEPS * 64];
__device__ int g_flag[64];
__device__ int g_ack[64];

__device__ __forceinline__ float4 ldcg4(const float* p) { return __ldcg((const float4*)p); }
__device__ __forceinline__ float2 ldcg2(const float* p) { return __ldcg((const float2*)p); }
__device__ __forceinline__ unsigned f2tf(float f) {
    unsigned r; asm("cvt.rna.tf32.f32 %0, %1;" : "=r"(r) : "f"(f)); return r;
}
__device__ __forceinline__ unsigned packbf(float lo, float hi) {
    unsigned r; asm("cvt.rn.bf16x2.f32 %0, %1, %2;" : "=r"(r) : "f"(hi), "f"(lo)); return r;
}
#define FU(x)  __float_as_uint(x)
#define UF(x)  __uint_as_float(x)

__device__ __forceinline__ void mma8(float c[4], const unsigned a[4],
                                     unsigned b0, unsigned b1)
{
    asm volatile(
        "mma.sync.aligned.m16n8k8.row.col.f32.tf32.tf32.f32 "
        "{%0,%1,%2,%3}, {%4,%5,%6,%7}, {%8,%9}, {%0,%1,%2,%3};"
        : "+f"(c[0]), "+f"(c[1]), "+f"(c[2]), "+f"(c[3])
        : "r"(a[0]), "r"(a[1]), "r"(a[2]), "r"(a[3]), "r"(b0), "r"(b1));
}
__device__ __forceinline__ void mma16(float c[4], const unsigned a[4],
                                      unsigned b0, unsigned b1)
{
    asm volatile(
        "mma.sync.aligned.m16n8k16.row.col.f32.bf16.bf16.f32 "
        "{%0,%1,%2,%3}, {%4,%5,%6,%7}, {%8,%9}, {%0,%1,%2,%3};"
        : "+f"(c[0]), "+f"(c[1]), "+f"(c[2]), "+f"(c[3])
        : "r"(a[0]), "r"(a[1]), "r"(a[2]), "r"(a[3]), "r"(b0), "r"(b1));
}

// ---------------- z0 --------------------------------------------------------
__global__ void z0_kernel(const float* __restrict__ cov,
                          const float* __restrict__ Wc1, const float* __restrict__ bc1,
                          const float* __restrict__ Wc2, const float* __restrict__ bc2)
{
    int b = blockIdx.x;
    int tid = threadIdx.x;  // 128
    __shared__ float sc[32];
    __shared__ float shh[64];
    if (tid < 32) sc[tid] = cov[b * 32 + tid];
    __syncthreads();
    if (tid < 64) {
        float acc = bc1[tid];
        #pragma unroll
        for (int c = 0; c < 32; c++) acc = fmaf(sc[c], Wc1[c * 64 + tid], acc);
        shh[tid] = fmaxf(acc, 0.f);
    }
    __syncthreads();
    float acc = bc2[tid];
    #pragma unroll
    for (int k = 0; k < 64; k++) acc = fmaf(shh[k], Wc2[k * 128 + tid], acc);
    float z = tanhf(acc);
    #pragma unroll
    for (int s = 0; s < SAMP; s++)
        g_z[(b * SAMP + s) * ZDIM + tid] = z;
}

// ---------------- Mt --------------------------------------------------------
__global__ void mt_kernel(const float* __restrict__ M)
{
    int i = blockIdx.x * blockDim.x + threadIdx.x;
    const float4* p = (const float4*)(M + (size_t)i * DIN);
    float s = 0.f;
    #pragma unroll
    for (int j = 0; j < DIN / 4; j++) { float4 v = p[j]; s += v.x + v.y + v.z + v.w; }
    g_Mt[i] = s * (1.f / (float)DIN);
}

// ---------------- weight transpose + bf16 pack ------------------------------
__global__ void transpose_bf16(const float* __restrict__ W, unsigned* __restrict__ WT,
                               int K, int N)
{
    int n  = blockIdx.x * 32 + (threadIdx.x & 31);
    int kp = blockIdx.y * 8 + (threadIdx.x >> 5);
    if (n < N && kp < K / 2) {
        float lo = W[(size_t)(2 * kp) * N + n];
        float hi = W[(size_t)(2 * kp + 1) * N + n];
        WT[(size_t)n * (K / 2) + kp] = packbf(lo, hi);
    }
}

// ---------------- tf32 MMA precompute GEMM body -----------------------------
__device__ __forceinline__ void gemm_body(
    const float* __restrict__ A, const float* __restrict__ A2,
    const float* __restrict__ W, const float* __restrict__ bias,
    float* __restrict__ C, int M, int N, int K, int act,
    float* sA, float* sB)
{
    const int tid = threadIdx.x;
    const int w = tid >> 5, lane = tid & 31, g = lane >> 2, tig = lane & 3;
    const int bm = blockIdx.y * 64, bn = blockIdx.x * 128;
    const int mt = w & 3, n0 = (w >> 2) * 32;
    float acc[4][4] = {};
    for (int k0 = 0; k0 < K; k0 += 32) {
        __syncthreads();
        {
            int r = tid >> 3, c4 = (tid & 7) * 4;
            float4 av = *(const float4*)&A[(size_t)(bm + r) * K + k0 + c4];
            if (A2) {
                float4 b4 = *(const float4*)&A2[(size_t)(bm + r) * K + k0 + c4];
                av.x += b4.x; av.y += b4.y; av.z += b4.z; av.w += b4.w;
            }
            float* d = &sA[r * 36 + c4];
            d[0] = UF(f2tf(av.x)); d[1] = UF(f2tf(av.y));
            d[2] = UF(f2tf(av.z)); d[3] = UF(f2tf(av.w));
        }
        #pragma unroll
        for (int l = 0; l < 2; l++) {
            int v = tid + l * 512;
            int r = v >> 5, c4 = (v & 31) * 4;
            float4 wv = *(const float4*)&W[(size_t)(k0 + r) * N + bn + c4];
            float* d = &sB[r * 136 + c4];
            d[0] = UF(f2tf(wv.x)); d[1] = UF(f2tf(wv.y));
            d[2] = UF(f2tf(wv.z)); d[3] = UF(f2tf(wv.w));
        }
        __syncthreads();
        const float* pA = sA + (mt * 16 + g) * 36 + tig;
        const float* pB = sB + tig * 136 + n0 + g;
        #pragma unroll
        for (int kk = 0; kk < 4; kk++) {
            unsigned a[4] = { FU(pA[kk*8]), FU(pA[kk*8 + 288]),
                              FU(pA[kk*8 + 4]), FU(pA[kk*8 + 292]) };
            #pragma unroll
            for (int nt = 0; nt < 4; nt++) {
                unsigned b0 = FU(pB[kk*8*136 + nt*8]);
                unsigned b1 = FU(pB[(kk*8 + 4)*136 + nt*8]);
                mma8(acc[nt], a, b0, b1);
            }
        }
    }
    #pragma unroll
    for (int nt = 0; nt < 4; nt++) {
        int cb = bn + n0 + nt * 8 + 2 * tig;
        float b0 = bias[cb], b1 = bias[cb + 1];
        #pragma unroll
        for (int rh = 0; rh < 2; rh++) {
            int row = bm + mt * 16 + g + rh * 8;
            float v0 = acc[nt][rh*2] + b0, v1 = acc[nt][rh*2 + 1] + b1;
            if (act == 1) { v0 = fmaxf(v0, 0.f); v1 = fmaxf(v1, 0.f); }
            if (act == 2) { v0 = expf(v0); v1 = expf(v1); }
            *(float2*)&C[(size_t)row * N + cb] = make_float2(v0, v1);
        }
    }
}

// Fused 4-way h-projection GEMM (blockIdx.z selects output)
__global__ void __launch_bounds__(512, 2)
gemm_pre4(const float* __restrict__ ph, const float* __restrict__ phpos,
          const float* __restrict__ Wd1, const float* __restrict__ bd1,
          const float* __restrict__ Wp1, const float* __restrict__ bp1,
          const float* __restrict__ Wf1, const float* __restrict__ bf1)
{
    __shared__ float sA[64 * 36];
    __shared__ float sB[32 * 136];
    const int which = blockIdx.z;
    const float* A2   = (which == 1) ? phpos : nullptr;
    const float* W    = (which <= 1) ? Wd1 : (which == 2 ? Wp1 : Wf1);
    const float* bias = (which <= 1) ? bd1 : (which == 2 ? bp1 : bf1);
    float* C = (which == 0) ? g_Hh : (which == 1 ? g_Hhpos : (which == 2 ? g_Hph : g_Hf));
    gemm_body(ph, A2, W, bias, C, TB, HDIM, RDIM, (which == 3) ? 1 : 0, sA, sB);
}

__global__ void __launch_bounds__(512, 2)
gemm_diff(const float* __restrict__ Wf2, const float* __restrict__ bf2)
{
    __shared__ float sA[64 * 36];
    __shared__ float sB[32 * 136];
    gemm_body(g_Hf, nullptr, Wf2, bf2, g_diff, TB, ZDIM, HDIM, 2, sA, sB);
}

// ================= bf16 pairwise scan (resident W2 in smem) =================
// Block 2g: drift. Block 2g+1: p-head/NLL. 16 rows per pair, 1 block/SM.

// smem offsets (float/uint units) in DYNAMIC shared memory
#define ZB    0        /* z bf16 packed [16][68]        */
#define SAP   1088     /* A_p bf16 [16][68]             */
#define SAQ   2176     /* A_q bf16 [16][68] / LVO fp32  */
#define HZB   3264     /* Hz fp32 [16][132]             */
#define BB2   5376     /* stream dbl buf 2 x [128][36]  */
#define W2R   14592    /* resident W2 bf16 [128][260]   */
#define RED   47872    /* [32]                          */
#define SH_TOT 47904
#define SMEM_BYTES (SH_TOT * 4)
#define LVO   SAQ

__device__ __forceinline__ void pf_ld(const unsigned* base, int tid,
                                      uint4& b0, uint4& b1)
{
    b0 = *(const uint4*)(base + (size_t)(tid >> 3) * 64 + (tid & 7) * 4);
    b1 = *(const uint4*)(base + (size_t)((tid + 512) >> 3) * 64 + ((tid + 512) & 7) * 4);
}
__device__ __forceinline__ void pf_st(unsigned* buf, int tid, uint4 b0, uint4 b1)
{
    *(uint4*)&buf[(tid >> 3) * 36 + (tid & 7) * 4] = b0;
    *(uint4*)&buf[((tid + 512) >> 3) * 36 + ((tid + 512) & 7) * 4] = b1;
}

// preload z fragments (8 k16-groups x 4 regs) from ZB
__device__ __forceinline__ void load_za(const unsigned* shu, int g, int tig,
                                        unsigned za[8][4])
{
    const unsigned* pz = shu + ZB + g * 68 + tig;
    #pragma unroll
    for (int kk = 0; kk < 8; kk++) {
        za[kk][0] = pz[kk*8];
        za[kk][1] = pz[kk*8 + 544];
        za[kk][2] = pz[kk*8 + 4];
        za[kk][3] = pz[kk*8 + 548];
    }
}

// load resident W2 [128][256] -> smem [128][260]
__device__ __forceinline__ void load_w2r(unsigned* shu, const unsigned* W2T, int tid)
{
    #pragma unroll
    for (int i = 0; i < 16; i++) {
        int v = tid + i * 512;                // 8192 uint4
        int r = v >> 6, c4 = (v & 63) * 4;
        *(uint4*)&shu[W2R + r * 260 + c4] = *(const uint4*)&W2T[(size_t)r * 256 + c4];
    }
}

__device__ void drift_step(int t, const float* __restrict__ bd2,
                           const float* __restrict__ noise,
                           float* sh, float zr[4], int gidx)
{
    unsigned* shu = (unsigned*)sh;
    const int tid = threadIdx.x;
    const int w = tid >> 5, lane = tid & 31, g = lane >> 2, tig = lane & 3;
    const int r0 = gidx * 16;
    const size_t hb = (size_t)t * BATCH * HDIM;

    unsigned za[8][4];
    load_za(shu, g, tig, za);

    uint4 br0, br1;
    pf_ld(g_Wd1zT, tid, br0, br1);   // stage 0: rows 0..128, kp 0..32

    float accp[4] = {0.f,0.f,0.f,0.f}, accq[4] = {0.f,0.f,0.f,0.f};

    for (int np = 0; np < 4; np++) {
        float ahz[4] = {0.f,0.f,0.f,0.f};
        #pragma unroll
        for (int st = 0; st < 2; st++) {
            int ss = np * 2 + st;
            unsigned* buf = shu + BB2 + (ss & 1) * 4608;
            pf_st(buf, tid, br0, br1);
            __syncthreads();
            if (ss < 7) {
                const unsigned* s = g_Wd1zT + (size_t)((ss + 1) >> 1) * 128 * 64
                                            + ((ss + 1) & 1) * 32;
                pf_ld(s, tid, br0, br1);
            }
            const unsigned* pB = buf + (w * 8 + g) * 36 + tig;
            #pragma unroll
            for (int kk = 0; kk < 4; kk++)
                mma16(ahz, za[st * 4 + kk], pB[kk*8], pB[kk*8 + 4]);
        }
        {   // export Hz fragments
            int cb = w * 8 + 2 * tig;
            *(float2*)&sh[HZB + g * 132 + cb]       = make_float2(ahz[0], ahz[1]);
            *(float2*)&sh[HZB + (g + 8) * 132 + cb] = make_float2(ahz[2], ahz[3]);
        }
        __syncthreads();
        #pragma unroll
        for (int l = 0; l < 2; l++) {   // A staging: relu(Hh/Hhpos + Hz) bf16
            int v = tid + l * 512;
            int arr = v >> 9, idx = v & 511;
            int r = idx >> 5, c4 = (idx & 31) * 4;
            int bi = (r0 + r) >> 3;
            const float* hs = arr ? g_Hhpos : g_Hh;
            float4 h4 = *(const float4*)&hs[hb + (size_t)bi * HDIM + np * 128 + c4];
            float4 z4 = *(const float4*)&sh[HZB + r * 132 + c4];
            unsigned u0 = packbf(fmaxf(h4.x + z4.x, 0.f), fmaxf(h4.y + z4.y, 0.f));
            unsigned u1 = packbf(fmaxf(h4.z + z4.z, 0.f), fmaxf(h4.w + z4.w, 0.f));
            *(uint2*)&shu[(arr ? SAQ : SAP) + r * 68 + (c4 >> 1)] = make_uint2(u0, u1);
        }
        __syncthreads();
        // drift dual MMA: resident W2R, NO syncs
        #pragma unroll
        for (int st2 = 0; st2 < 2; st2++) {
            const unsigned* pAp = shu + SAP + g * 68 + st2 * 32 + tig;
            const unsigned* pAq = shu + SAQ + g * 68 + st2 * 32 + tig;
            const unsigned* pB2 = shu + W2R + (w * 8 + g) * 260 + np * 64 + st2 * 32 + tig;
            #pragma unroll
            for (int kk = 0; kk < 4; kk++) {
                unsigned ap[4] = { pAp[kk*8], pAp[kk*8 + 544], pAp[kk*8 + 4], pAp[kk*8 + 548] };
                unsigned aq[4] = { pAq[kk*8], pAq[kk*8 + 544], pAq[kk*8 + 4], pAq[kk*8 + 548] };
                unsigned b0 = pB2[kk*8], b1 = pB2[kk*8 + 4];
                mma16(accp, ap, b0, b1);
                mma16(accq, aq, b0, b1);
            }
        }
    }

    // ---- epilogue: prior/poster, z update, KLD ----
    if (tid == 0) {
        while (((volatile int*)g_ack)[gidx] < t) __nanosleep(64);
    }
    __syncthreads();
    const int c = w * 8 + 2 * tig;
    float2 bia = *(const float2*)&bd2[c];
    float kl = 0.f;
    #pragma unroll
    for (int rh = 0; rh < 2; rh++) {
        int row = r0 + g + rh * 8;
        int bi = row >> 3, si = row & 7;
        float2 dv = *(const float2*)&g_diff[((size_t)t * BATCH + bi) * ZDIM + c];
        float2 ev = *(const float2*)&noise[(((size_t)t * BATCH + bi) * SAMP + si) * ZDIM + c];
        float pr0 = 0.1f * tanhf(accp[rh*2]     + bia.x);
        float pr1 = 0.1f * tanhf(accp[rh*2 + 1] + bia.y);
        float po0 = 0.1f * tanhf(accq[rh*2]     + bia.x);
        float po1 = 0.1f * tanhf(accq[rh*2 + 1] + bia.y);
        zr[rh*2]     += DT * po0 + SQRT_DT * dv.x * ev.x;
        zr[rh*2 + 1] += DT * po1 + SQRT_DT * dv.y * ev.y;
        __stcg((float2*)&g_z[(size_t)row * ZDIM + c], make_float2(zr[rh*2], zr[rh*2 + 1]));
        shu[ZB + (g + rh * 8) * 68 + (c >> 1)] = packbf(zr[rh*2], zr[rh*2 + 1]);
        float e0 = (pr0 - po0) / dv.x;
        float e1 = (pr1 - po1) / dv.y;
        kl += e0 * e0 + e1 * e1;
    }
    __threadfence();
    __syncthreads();
    if (tid == 0) ((volatile int*)g_flag)[gidx] = t + 1;
    #pragma unroll
    for (int o = 16; o > 0; o >>= 1) kl += __shfl_xor_sync(~0u, kl, o);
    if (lane == 0) sh[RED + w] = kl;
    __syncthreads();
    if (tid < 32) {
        float v = (tid < 16) ? sh[RED + tid] : 0.f;
        #pragma unroll
        for (int o = 8; o > 0; o >>= 1) v += __shfl_xor_sync(~0u, v, o);
        if (tid == 0) g_kldpart[t * 64 + gidx] = v;
    }
    __syncthreads();
}

__device__ void p_step(int t, const float* __restrict__ bp2,
                       const float* __restrict__ X, float* sh, int gidx)
{
    unsigned* shu = (unsigned*)sh;
    const int tid = threadIdx.x;
    const int w = tid >> 5, lane = tid & 31, g = lane >> 2, tig = lane & 3;
    const int r0 = gidx * 16;
    const size_t hb = (size_t)t * BATCH * HDIM;

    uint4 br0, br1;
    pf_ld(g_Wp1zT, tid, br0, br1);

    // wait for z(t+1), stage to ZB bf16
    if (tid == 0) {
        while (((volatile int*)g_flag)[gidx] < t + 1) __nanosleep(64);
        __threadfence();
    }
    __syncthreads();
    {
        int r = tid >> 5, c4 = (tid & 31) * 4;
        float4 z4 = ldcg4(&g_z[(size_t)(r0 + r) * ZDIM + c4]);
        shu[ZB + r * 68 + (c4 >> 1)]     = packbf(z4.x, z4.y);
        shu[ZB + r * 68 + (c4 >> 1) + 1] = packbf(z4.z, z4.w);
    }
    __syncthreads();
    if (tid == 0) {
        __threadfence();
        ((volatile int*)g_ack)[gidx] = t + 1;
    }

    unsigned za[8][4];
    load_za(shu, g, tig, za);

    float acc[4] = {0.f,0.f,0.f,0.f};
    for (int np = 0; np < 4; np++) {
        float ahz[4] = {0.f,0.f,0.f,0.f};
        #pragma unroll
        for (int st = 0; st < 2; st++) {
            int ss = np * 2 + st;
            unsigned* buf = shu + BB2 + (ss & 1) * 4608;
            pf_st(buf, tid, br0, br1);
            __syncthreads();
            if (ss < 7) {
                const unsigned* s = g_Wp1zT + (size_t)((ss + 1) >> 1) * 128 * 64
                                            + ((ss + 1) & 1) * 32;
                pf_ld(s, tid, br0, br1);
            }
            const unsigned* pB = buf + (w * 8 + g) * 36 + tig;
            #pragma unroll
            for (int kk = 0; kk < 4; kk++)
                mma16(ahz, za[st * 4 + kk], pB[kk*8], pB[kk*8 + 4]);
        }
        {
            int cb = w * 8 + 2 * tig;
            *(float2*)&sh[HZB + g * 132 + cb]       = make_float2(ahz[0], ahz[1]);
            *(float2*)&sh[HZB + (g + 8) * 132 + cb] = make_float2(ahz[2], ahz[3]);
        }
        __syncthreads();
        {   // A staging: relu(Hph + Hpz) bf16
            int r = tid >> 5, c4 = (tid & 31) * 4;
            int bi = (r0 + r) >> 3;
            float4 h4 = *(const float4*)&g_Hph[hb + (size_t)bi * HDIM + np * 128 + c4];
            float4 z4 = *(const float4*)&sh[HZB + r * 132 + c4];
            unsigned u0 = packbf(fmaxf(h4.x + z4.x, 0.f), fmaxf(h4.y + z4.y, 0.f));
            unsigned u1 = packbf(fmaxf(h4.z + z4.z, 0.f), fmaxf(h4.w + z4.w, 0.f));
            *(uint2*)&shu[SAP + r * 68 + (c4 >> 1)] = make_uint2(u0, u1);
        }
        __syncthreads();
        #pragma unroll
        for (int st2 = 0; st2 < 2; st2++) {
            const unsigned* pAp = shu + SAP + g * 68 + st2 * 32 + tig;
            const unsigned* pB2 = shu + W2R + (w * 8 + g) * 260 + np * 64 + st2 * 32 + tig;
            #pragma unroll
            for (int kk = 0; kk < 4; kk++) {
                unsigned ap[4] = { pAp[kk*8], pAp[kk*8 + 544], pAp[kk*8 + 4], pAp[kk*8 + 548] };
                mma16(acc, ap, pB2[kk*8], pB2[kk*8 + 4]);
            }
        }
    }

    // ---- NLL epilogue ----
    __syncthreads();
    if (w >= 8) {   // logvar warps: export acc+bias (cols 64..127)
        int cb = (w - 8) * 8 + 2 * tig;
        float2 bia = *(const float2*)&bp2[64 + cb];
        *(float2*)&sh[LVO + g * 68 + cb]       = make_float2(acc[0] + bia.x, acc[1] + bia.y);
        *(float2*)&sh[LVO + (g + 8) * 68 + cb] = make_float2(acc[2] + bia.x, acc[3] + bia.y);
    }
    __syncthreads();
    float local = 0.f;
    if (w < 8) {
        int mc = w * 8 + 2 * tig;
        float2 bia = *(const float2*)&bp2[mc];
        #pragma unroll
        for (int rh = 0; rh < 2; rh++) {
            int row = r0 + g + rh * 8;
            int bi = row >> 3;
            float mt = g_Mt[t * BATCH + bi];
            float2 lv = *(float2*)&sh[LVO + (g + rh * 8) * 68 + mc];
            float2 xv = *(const float2*)&X[((size_t)t * BATCH + bi) * DIN + mc];
            float m0 = acc[rh*2] + bia.x, m1 = acc[rh*2 + 1] + bia.y;
            float d0 = xv.x - m0, d1 = xv.y - m1;
            local += mt * 0.5f * (LOG_2PI + lv.x + d0 * d0 * expf(-lv.x));
            local += mt * 0.5f * (LOG_2PI + lv.y + d1 * d1 * expf(-lv.y));
        }
    }
    #pragma unroll
    for (int o = 16; o > 0; o >>= 1) local += __shfl_xor_sync(~0u, local, o);
    if (lane == 0) sh[RED + w] = local;
    __syncthreads();
    if (tid < 32) {
        float v = (tid < 16) ? sh[RED + tid] : 0.f;
        #pragma unroll
        for (int o = 8; o > 0; o >>= 1) v += __shfl_xor_sync(~0u, v, o);
        if (tid == 0) g_reconpart[t * 64 + gidx] = v;
    }
    __syncthreads();
}

__global__ void __launch_bounds__(NTHR, 1)
scan_pairs(const float* __restrict__ bd2, const float* __restrict__ noise,
           const float* __restrict__ bp2, const float* __restrict__ X)
{
    extern __shared__ float sh[];
    unsigned* shu = (unsigned*)sh;
    const int role = blockIdx.x & 1;
    const int gidx = blockIdx.x >> 1;
    const int tid = threadIdx.x;
    const int w = tid >> 5, lane = tid & 31, g = lane >> 2, tig = lane & 3;
    const int r0 = gidx * 16;

    // resident W2 (once per kernel)
    load_w2r(shu, role ? g_Wp2T : g_Wd2T, tid);

    if (role == 0) {
        {   // init ZB (bf16) from z0
            int r = tid >> 5, c4 = (tid & 31) * 4;
            float4 z4 = ldcg4(&g_z[(size_t)(r0 + r) * ZDIM + c4]);
            shu[ZB + r * 68 + (c4 >> 1)]     = packbf(z4.x, z4.y);
            shu[ZB + r * 68 + (c4 >> 1) + 1] = packbf(z4.z, z4.w);
        }
        float zr[4];
        {
            int c = w * 8 + 2 * tig;
            float2 a = ldcg2(&g_z[(size_t)(r0 + g) * ZDIM + c]);
            float2 b = ldcg2(&g_z[(size_t)(r0 + g + 8) * ZDIM + c]);
            zr[0] = a.x; zr[1] = a.y; zr[2] = b.x; zr[3] = b.y;
        }
        __syncthreads();
        for (int t = 0; t < T_STEPS; t++)
            drift_step(t, bd2, noise, sh, zr, gidx);
    } else {
        __syncthreads();
        for (int t = 0; t < T_STEPS; t++)
            p_step(t, bp2, X, sh, gidx);
    }
}

// ---------------- outputs ---------------------------------------------------
__global__ void copy_z(float* __restrict__ out)
{
    int i = blockIdx.x * blockDim.x + threadIdx.x;
    out[i] = g_z[i];
}

__global__ void finalize(float* __restrict__ out, int out_size)
{
    int tid = threadIdx.x;   // 256
    if (tid < 64) { g_flag[tid] = 0; g_ack[tid] = 0; }   // reset for graph replay
    float k = 0.f, r = 0.f;
    for (int i = tid; i < T_STEPS * 64; i += 256) k += g_kldpart[i];
    for (int i = tid; i < T_STEPS * 64; i += 256) r += g_reconpart[i];
    __shared__ float rk[256], rr[256];
    rk[tid] = k; rr[tid] = r;
    __syncthreads();
    for (int s = 128; s > 0; s >>= 1) {
        if (tid < s) { rk[tid] += rk[tid + s]; rr[tid] += rr[tid + s]; }
        __syncthreads();
    }
    if (tid == 0) {
        float kld   = rk[0] * (0.5f * DT / (float)BS);
        float recon = rr[0] * (1.f / (float)BS);
        out[out_size - 3] = recon + kld;
        out[out_size - 2] = recon;
        out[out_size - 1] = kld;
    }
}

// ---------------- launch ----------------------------------------------------
extern "C" void kernel_launch(void* const* d_in, const int* in_sizes, int n_in,
                              void* d_out, int out_size)
{
    const float* X     = (const float*)d_in[0];
    const float* M     = (const float*)d_in[1];
    const float* cov   = (const float*)d_in[2];
    const float* ph    = (const float*)d_in[3];
    const float* phpos = (const float*)d_in[4];
    const float* noise = (const float*)d_in[5];
    const float* Wc1 = (const float*)d_in[6],  *bc1 = (const float*)d_in[7];
    const float* Wc2 = (const float*)d_in[8],  *bc2 = (const float*)d_in[9];
    const float* Wd1 = (const float*)d_in[10], *bd1 = (const float*)d_in[11];
    const float* Wd2 = (const float*)d_in[12], *bd2 = (const float*)d_in[13];
    const float* Wf1 = (const float*)d_in[14], *bf1 = (const float*)d_in[15];
    const float* Wf2 = (const float*)d_in[16], *bf2 = (const float*)d_in[17];
    const float* Wp1 = (const float*)d_in[18], *bp1 = (const float*)d_in[19];
    const float* Wp2 = (const float*)d_in[20], *bp2 = (const float*)d_in[21];
    float* out = (float*)d_out;

    unsigned *pWd1zT, *pWd2T, *pWp1zT, *pWp2T;
    cudaGetSymbolAddress((void**)&pWd1zT, g_Wd1zT);
    cudaGetSymbolAddress((void**)&pWd2T,  g_Wd2T);
    cudaGetSymbolAddress((void**)&pWp1zT, g_Wp1zT);
    cudaGetSymbolAddress((void**)&pWp2T,  g_Wp2T);

    static int smem_set = 0;
    if (!smem_set) {
        cudaFuncSetAttribute(scan_pairs,
                             cudaFuncAttributeMaxDynamicSharedMemorySize, SMEM_BYTES);
        smem_set = 1;
    }

    // ---- precompute ----
    z0_kernel<<<BATCH, 128>>>(cov, Wc1, bc1, Wc2, bc2);
    mt_kernel<<<64, 256>>>(M);
    transpose_bf16<<<dim3(16, 8),  256>>>(Wd1 + RDIM * HDIM, pWd1zT, ZDIM, HDIM);
    transpose_bf16<<<dim3(4, 32),  256>>>(Wd2,               pWd2T,  HDIM, ZDIM);
    transpose_bf16<<<dim3(16, 8),  256>>>(Wp1 + RDIM * HDIM, pWp1zT, ZDIM, HDIM);
    transpose_bf16<<<dim3(4, 32),  256>>>(Wp2,               pWp2T,  HDIM, ZDIM);
    gemm_pre4<<<dim3(4, 256, 4), 512>>>(ph, phpos, Wd1, bd1, Wp1, bp1, Wf1, bf1);
    gemm_diff<<<dim3(1, 256), 512>>>(Wf2, bf2);

    // ---- bf16 pairwise scan (resident W2) ----
    scan_pairs<<<128, NTHR, SMEM_BYTES>>>(bd2, noise, bp2, X);

    // ---- outputs ----
    copy_z<<<(BS * ZDIM) / 256, 256>>>(out);
    finalize<<<1, 256>>>(out, out_size);
}

// round 9
// speedup vs baseline: 3.3030x; 1.2279x over previous
#include <cuda_runtime.h>
#include <math.h>
#include <stdint.h>

#define T_STEPS 128
#define BATCH   128
#define SAMP    8
#define DIN     64
#define RDIM    256
#define ZDIM    128
#define HDIM    512
#define BS      1024
#define TB      16384
#define NTHR    512

#define DT       0.05f
#define SQRT_DT  0.22360679774997896f
#define LOG_2PI  1.8378770664093453f

// ---------------- scratch ---------------------------------------------------
__device__ __align__(16) float g_Hh[TB * HDIM];
__device__ __align__(16) float g_Hhpos[TB * HDIM];
__device__ __align__(16) float g_Hph[TB * HDIM];
__device__ __align__(16) float g_Hf[TB * HDIM];
__device__ __align__(16) float g_diff[TB * ZDIM];
__device__ __align__(16) float g_Mt[T_STEPS * BATCH];
__device__ __align__(16) float g_z[BS * ZDIM];
// bf16 transposed weights: WT[n][k/2] packed pairs (k even lo, k odd hi)
__device__ __align__(16) unsigned g_Wd1zT[HDIM * ZDIM / 2];  // [512][64]
__device__ __align__(16) unsigned g_Wd2T[ZDIM * HDIM / 2];   // [128][256]
__device__ __align__(16) unsigned g_Wp1zT[HDIM * ZDIM / 2];  // [512][64]
__device__ __align__(16) unsigned g_Wp2T[ZDIM * HDIM / 2];   // [128][256]
__device__ float g_kldpart[T_STEPS * 64];
__device__ float g_reconpart[T_STEPS * 64];
__device__ int g_flag[64];
__device__ int g_ack[64];

__device__ __forceinline__ float4 ldcg4(const float* p) { return __ldcg((const float4*)p); }
__device__ __forceinline__ float2 ldcg2(const float* p) { return __ldcg((const float2*)p); }
__device__ __forceinline__ unsigned f2tf(float f) {
    unsigned r; asm("cvt.rna.tf32.f32 %0, %1;" : "=r"(r) : "f"(f)); return r;
}
__device__ __forceinline__ unsigned packbf(float lo, float hi) {
    unsigned r; asm("cvt.rn.bf16x2.f32 %0, %1, %2;" : "=r"(r) : "f"(hi), "f"(lo)); return r;
}
#define FU(x)  __float_as_uint(x)
#define UF(x)  __uint_as_float(x)

__device__ __forceinline__ void mma8(float c[4], const unsigned a[4],
                                     unsigned b0, unsigned b1)
{
    asm volatile(
        "mma.sync.aligned.m16n8k8.row.col.f32.tf32.tf32.f32 "
        "{%0,%1,%2,%3}, {%4,%5,%6,%7}, {%8,%9}, {%0,%1,%2,%3};"
        : "+f"(c[0]), "+f"(c[1]), "+f"(c[2]), "+f"(c[3])
        : "r"(a[0]), "r"(a[1]), "r"(a[2]), "r"(a[3]), "r"(b0), "r"(b1));
}
__device__ __forceinline__ void mma16(float c[4], const unsigned a[4],
                                      unsigned b0, unsigned b1)
{
    asm volatile(
        "mma.sync.aligned.m16n8k16.row.col.f32.bf16.bf16.f32 "
        "{%0,%1,%2,%3}, {%4,%5,%6,%7}, {%8,%9}, {%0,%1,%2,%3};"
        : "+f"(c[0]), "+f"(c[1]), "+f"(c[2]), "+f"(c[3])
        : "r"(a[0]), "r"(a[1]), "r"(a[2]), "r"(a[3]), "r"(b0), "r"(b1));
}

// ---------------- z0 --------------------------------------------------------
__global__ void z0_kernel(const float* __restrict__ cov,
                          const float* __restrict__ Wc1, const float* __restrict__ bc1,
                          const float* __restrict__ Wc2, const float* __restrict__ bc2)
{
    int b = blockIdx.x;
    int tid = threadIdx.x;  // 128
    __shared__ float sc[32];
    __shared__ float shh[64];
    if (tid < 32) sc[tid] = cov[b * 32 + tid];
    __syncthreads();
    if (tid < 64) {
        float acc = bc1[tid];
        #pragma unroll
        for (int c = 0; c < 32; c++) acc = fmaf(sc[c], Wc1[c * 64 + tid], acc);
        shh[tid] = fmaxf(acc, 0.f);
    }
    __syncthreads();
    float acc = bc2[tid];
    #pragma unroll
    for (int k = 0; k < 64; k++) acc = fmaf(shh[k], Wc2[k * 128 + tid], acc);
    float z = tanhf(acc);
    #pragma unroll
    for (int s = 0; s < SAMP; s++)
        g_z[(b * SAMP + s) * ZDIM + tid] = z;
}

// ---------------- Mt --------------------------------------------------------
__global__ void mt_kernel(const float* __restrict__ M)
{
    int i = blockIdx.x * blockDim.x + threadIdx.x;
    const float4* p = (const float4*)(M + (size_t)i * DIN);
    float s = 0.f;
    #pragma unroll
    for (int j = 0; j < DIN / 4; j++) { float4 v = p[j]; s += v.x + v.y + v.z + v.w; }
    g_Mt[i] = s * (1.f / (float)DIN);
}

// ---------------- weight transpose + bf16 pack ------------------------------
__global__ void transpose_bf16(const float* __restrict__ W, unsigned* __restrict__ WT,
                               int K, int N)
{
    int n  = blockIdx.x * 32 + (threadIdx.x & 31);
    int kp = blockIdx.y * 8 + (threadIdx.x >> 5);
    if (n < N && kp < K / 2) {
        float lo = W[(size_t)(2 * kp) * N + n];
        float hi = W[(size_t)(2 * kp + 1) * N + n];
        WT[(size_t)n * (K / 2) + kp] = packbf(lo, hi);
    }
}

// ---------------- tf32 MMA precompute GEMM body -----------------------------
__device__ __forceinline__ void gemm_body(
    const float* __restrict__ A, const float* __restrict__ A2,
    const float* __restrict__ W, const float* __restrict__ bias,
    float* __restrict__ C, int M, int N, int K, int act,
    float* sA, float* sB)
{
    const int tid = threadIdx.x;
    const int w = tid >> 5, lane = tid & 31, g = lane >> 2, tig = lane & 3;
    const int bm = blockIdx.y * 64, bn = blockIdx.x * 128;
    const int mt = w & 3, n0 = (w >> 2) * 32;
    float acc[4][4] = {};
    for (int k0 = 0; k0 < K; k0 += 32) {
        __syncthreads();
        {
            int r = tid >> 3, c4 = (tid & 7) * 4;
            float4 av = *(const float4*)&A[(size_t)(bm + r) * K + k0 + c4];
            if (A2) {
                float4 b4 = *(const float4*)&A2[(size_t)(bm + r) * K + k0 + c4];
                av.x += b4.x; av.y += b4.y; av.z += b4.z; av.w += b4.w;
            }
            float* d = &sA[r * 36 + c4];
            d[0] = UF(f2tf(av.x)); d[1] = UF(f2tf(av.y));
            d[2] = UF(f2tf(av.z)); d[3] = UF(f2tf(av.w));
        }
        #pragma unroll
        for (int l = 0; l < 2; l++) {
            int v = tid + l * 512;
            int r = v >> 5, c4 = (v & 31) * 4;
            float4 wv = *(const float4*)&W[(size_t)(k0 + r) * N + bn + c4];
            float* d = &sB[r * 136 + c4];
            d[0] = UF(f2tf(wv.x)); d[1] = UF(f2tf(wv.y));
            d[2] = UF(f2tf(wv.z)); d[3] = UF(f2tf(wv.w));
        }
        __syncthreads();
        const float* pA = sA + (mt * 16 + g) * 36 + tig;
        const float* pB = sB + tig * 136 + n0 + g;
        #pragma unroll
        for (int kk = 0; kk < 4; kk++) {
            unsigned a[4] = { FU(pA[kk*8]), FU(pA[kk*8 + 288]),
                              FU(pA[kk*8 + 4]), FU(pA[kk*8 + 292]) };
            #pragma unroll
            for (int nt = 0; nt < 4; nt++) {
                unsigned b0 = FU(pB[kk*8*136 + nt*8]);
                unsigned b1 = FU(pB[(kk*8 + 4)*136 + nt*8]);
                mma8(acc[nt], a, b0, b1);
            }
        }
    }
    #pragma unroll
    for (int nt = 0; nt < 4; nt++) {
        int cb = bn + n0 + nt * 8 + 2 * tig;
        float b0 = bias[cb], b1 = bias[cb + 1];
        #pragma unroll
        for (int rh = 0; rh < 2; rh++) {
            int row = bm + mt * 16 + g + rh * 8;
            float v0 = acc[nt][rh*2] + b0, v1 = acc[nt][rh*2 + 1] + b1;
            if (act == 1) { v0 = fmaxf(v0, 0.f); v1 = fmaxf(v1, 0.f); }
            if (act == 2) { v0 = expf(v0); v1 = expf(v1); }
            *(float2*)&C[(size_t)row * N + cb] = make_float2(v0, v1);
        }
    }
}

// Fused 4-way h-projection GEMM (blockIdx.z selects output)
__global__ void __launch_bounds__(512, 2)
gemm_pre4(const float* __restrict__ ph, const float* __restrict__ phpos,
          const float* __restrict__ Wd1, const float* __restrict__ bd1,
          const float* __restrict__ Wp1, const float* __restrict__ bp1,
          const float* __restrict__ Wf1, const float* __restrict__ bf1)
{
    __shared__ float sA[64 * 36];
    __shared__ float sB[32 * 136];
    const int which = blockIdx.z;
    const float* A2   = (which == 1) ? phpos : nullptr;
    const float* W    = (which <= 1) ? Wd1 : (which == 2 ? Wp1 : Wf1);
    const float* bias = (which <= 1) ? bd1 : (which == 2 ? bp1 : bf1);
    float* C = (which == 0) ? g_Hh : (which == 1 ? g_Hhpos : (which == 2 ? g_Hph : g_Hf));
    gemm_body(ph, A2, W, bias, C, TB, HDIM, RDIM, (which == 3) ? 1 : 0, sA, sB);
}

__global__ void __launch_bounds__(512, 2)
gemm_diff(const float* __restrict__ Wf2, const float* __restrict__ bf2)
{
    __shared__ float sA[64 * 36];
    __shared__ float sB[32 * 136];
    gemm_body(g_Hf, nullptr, Wf2, bf2, g_diff, TB, ZDIM, HDIM, 2, sA, sB);
}

// ================= bf16 pairwise scan (resident W2 in smem) =================
// Block 2g: drift. Block 2g+1: p-head/NLL. 16 rows per pair, 1 block/SM.

// smem offsets (float/uint units) in DYNAMIC shared memory
#define ZB    0        /* z bf16 packed [16][68]        */
#define SAP   1088     /* A_p bf16 [16][68]             */
#define SAQ   2176     /* A_q bf16 [16][68] / LVO fp32  */
#define HZB   3264     /* Hz fp32 [16][132]             */
#define BB2   5376     /* stream dbl buf 2 x [128][36]  */
#define W2R   14592    /* resident W2 bf16 [128][260]   */
#define RED   47872    /* [32]                          */
#define SH_TOT 47904
#define SMEM_BYTES (SH_TOT * 4)
#define LVO   SAQ

__device__ __forceinline__ void pf_ld(const unsigned* base, int tid,
                                      uint4& b0, uint4& b1)
{
    b0 = *(const uint4*)(base + (size_t)(tid >> 3) * 64 + (tid & 7) * 4);
    b1 = *(const uint4*)(base + (size_t)((tid + 512) >> 3) * 64 + ((tid + 512) & 7) * 4);
}
__device__ __forceinline__ void pf_st(unsigned* buf, int tid, uint4 b0, uint4 b1)
{
    *(uint4*)&buf[(tid >> 3) * 36 + (tid & 7) * 4] = b0;
    *(uint4*)&buf[((tid + 512) >> 3) * 36 + ((tid + 512) & 7) * 4] = b1;
}

// preload z fragments (8 k16-groups x 4 regs) from ZB
__device__ __forceinline__ void load_za(const unsigned* shu, int g, int tig,
                                        unsigned za[8][4])
{
    const unsigned* pz = shu + ZB + g * 68 + tig;
    #pragma unroll
    for (int kk = 0; kk < 8; kk++) {
        za[kk][0] = pz[kk*8];
        za[kk][1] = pz[kk*8 + 544];
        za[kk][2] = pz[kk*8 + 4];
        za[kk][3] = pz[kk*8 + 548];
    }
}

// load resident W2 [128][256] -> smem [128][260]
__device__ __forceinline__ void load_w2r(unsigned* shu, const unsigned* W2T, int tid)
{
    #pragma unroll
    for (int i = 0; i < 16; i++) {
        int v = tid + i * 512;                // 8192 uint4
        int r = v >> 6, c4 = (v & 63) * 4;
        *(uint4*)&shu[W2R + r * 260 + c4] = *(const uint4*)&W2T[(size_t)r * 256 + c4];
    }
}

__device__ void drift_step(int t, const float* __restrict__ bd2,
                           const float* __restrict__ noise,
                           float* sh, float zr[4], int gidx,
                           float* __restrict__ out)
{
    unsigned* shu = (unsigned*)sh;
    const int tid = threadIdx.x;
    const int w = tid >> 5, lane = tid & 31, g = lane >> 2, tig = lane & 3;
    const int r0 = gidx * 16;
    const size_t hb = (size_t)t * BATCH * HDIM;

    // ---- step-top prefetches (all in flight before any compute) ----
    uint4 br0, br1;
    pf_ld(g_Wd1zT, tid, br0, br1);                 // weight stage 0
    const int sr = tid >> 5, sc4 = (tid & 31) * 4; // staging slot (16x128 tile)
    const int sbi = (r0 + sr) >> 3;
    float4 hA = *(const float4*)&g_Hh[hb + (size_t)sbi * HDIM + sc4];     // np=0
    float4 hB = *(const float4*)&g_Hhpos[hb + (size_t)sbi * HDIM + sc4];
    const int c = w * 8 + 2 * tig;
    const int bi0 = (r0 + g) >> 3,     si0 = (r0 + g) & 7;
    const int bi1 = (r0 + g + 8) >> 3, si1 = (r0 + g + 8) & 7;
    float2 dva = ldcg2(&g_diff[((size_t)t * BATCH + bi0) * ZDIM + c]);
    float2 dvb = ldcg2(&g_diff[((size_t)t * BATCH + bi1) * ZDIM + c]);
    float2 eva = ldcg2(&noise[(((size_t)t * BATCH + bi0) * SAMP + si0) * ZDIM + c]);
    float2 evb = ldcg2(&noise[(((size_t)t * BATCH + bi1) * SAMP + si1) * ZDIM + c]);
    float2 bia = *(const float2*)&bd2[c];

    unsigned za[8][4];
    load_za(shu, g, tig, za);

    float accp[4] = {0.f,0.f,0.f,0.f}, accq[4] = {0.f,0.f,0.f,0.f};

    for (int np = 0; np < 4; np++) {
        float ahz[4] = {0.f,0.f,0.f,0.f};
        #pragma unroll
        for (int st = 0; st < 2; st++) {
            int ss = np * 2 + st;
            unsigned* buf = shu + BB2 + (ss & 1) * 4608;
            pf_st(buf, tid, br0, br1);
            __syncthreads();
            if (ss < 7) {
                const unsigned* s = g_Wd1zT + (size_t)((ss + 1) >> 1) * 128 * 64
                                            + ((ss + 1) & 1) * 32;
                pf_ld(s, tid, br0, br1);
            }
            const unsigned* pB = buf + (w * 8 + g) * 36 + tig;
            #pragma unroll
            for (int kk = 0; kk < 4; kk++)
                mma16(ahz, za[st * 4 + kk], pB[kk*8], pB[kk*8 + 4]);
        }
        {   // export Hz fragments
            int cb = w * 8 + 2 * tig;
            *(float2*)&sh[HZB + g * 132 + cb]       = make_float2(ahz[0], ahz[1]);
            *(float2*)&sh[HZB + (g + 8) * 132 + cb] = make_float2(ahz[2], ahz[3]);
        }
        __syncthreads();
        {   // A staging from prefetched h tiles + HZB
            float4 z4 = *(const float4*)&sh[HZB + sr * 132 + sc4];
            unsigned p0 = packbf(fmaxf(hA.x + z4.x, 0.f), fmaxf(hA.y + z4.y, 0.f));
            unsigned p1 = packbf(fmaxf(hA.z + z4.z, 0.f), fmaxf(hA.w + z4.w, 0.f));
            unsigned q0 = packbf(fmaxf(hB.x + z4.x, 0.f), fmaxf(hB.y + z4.y, 0.f));
            unsigned q1 = packbf(fmaxf(hB.z + z4.z, 0.f), fmaxf(hB.w + z4.w, 0.f));
            *(uint2*)&shu[SAP + sr * 68 + (sc4 >> 1)] = make_uint2(p0, p1);
            *(uint2*)&shu[SAQ + sr * 68 + (sc4 >> 1)] = make_uint2(q0, q1);
            if (np < 3) {   // prefetch next np (in flight across dual GEMM + Hz stages)
                hA = *(const float4*)&g_Hh[hb + (size_t)sbi * HDIM + (np + 1) * 128 + sc4];
                hB = *(const float4*)&g_Hhpos[hb + (size_t)sbi * HDIM + (np + 1) * 128 + sc4];
            }
        }
        __syncthreads();
        // drift dual MMA: resident W2R, NO syncs
        #pragma unroll
        for (int st2 = 0; st2 < 2; st2++) {
            const unsigned* pAp = shu + SAP + g * 68 + st2 * 32 + tig;
            const unsigned* pAq = shu + SAQ + g * 68 + st2 * 32 + tig;
            const unsigned* pB2 = shu + W2R + (w * 8 + g) * 260 + np * 64 + st2 * 32 + tig;
            #pragma unroll
            for (int kk = 0; kk < 4; kk++) {
                unsigned ap[4] = { pAp[kk*8], pAp[kk*8 + 544], pAp[kk*8 + 4], pAp[kk*8 + 548] };
                unsigned aq[4] = { pAq[kk*8], pAq[kk*8 + 544], pAq[kk*8 + 4], pAq[kk*8 + 548] };
                unsigned b0 = pB2[kk*8], b1 = pB2[kk*8 + 4];
                mma16(accp, ap, b0, b1);
                mma16(accq, aq, b0, b1);
            }
        }
    }

    // ---- epilogue: prior/poster, z update, KLD (operands prefetched) ----
    if (tid == 0) {
        while (((volatile int*)g_ack)[gidx] < t) __nanosleep(64);
    }
    __syncthreads();
    float kl = 0.f;
    {
        float pr0 = 0.1f * tanhf(accp[0] + bia.x);
        float pr1 = 0.1f * tanhf(accp[1] + bia.y);
        float po0 = 0.1f * tanhf(accq[0] + bia.x);
        float po1 = 0.1f * tanhf(accq[1] + bia.y);
        zr[0] += DT * po0 + SQRT_DT * dva.x * eva.x;
        zr[1] += DT * po1 + SQRT_DT * dva.y * eva.y;
        __stcg((float2*)&g_z[(size_t)(r0 + g) * ZDIM + c], make_float2(zr[0], zr[1]));
        if (t == T_STEPS - 1)
            *(float2*)&out[(size_t)(r0 + g) * ZDIM + c] = make_float2(zr[0], zr[1]);
        shu[ZB + g * 68 + (c >> 1)] = packbf(zr[0], zr[1]);
        float e0 = (pr0 - po0) / dva.x;
        float e1 = (pr1 - po1) / dva.y;
        kl += e0 * e0 + e1 * e1;
    }
    {
        float pr0 = 0.1f * tanhf(accp[2] + bia.x);
        float pr1 = 0.1f * tanhf(accp[3] + bia.y);
        float po0 = 0.1f * tanhf(accq[2] + bia.x);
        float po1 = 0.1f * tanhf(accq[3] + bia.y);
        zr[2] += DT * po0 + SQRT_DT * dvb.x * evb.x;
        zr[3] += DT * po1 + SQRT_DT * dvb.y * evb.y;
        __stcg((float2*)&g_z[(size_t)(r0 + g + 8) * ZDIM + c], make_float2(zr[2], zr[3]));
        if (t == T_STEPS - 1)
            *(float2*)&out[(size_t)(r0 + g + 8) * ZDIM + c] = make_float2(zr[2], zr[3]);
        shu[ZB + (g + 8) * 68 + (c >> 1)] = packbf(zr[2], zr[3]);
        float e0 = (pr0 - po0) / dvb.x;
        float e1 = (pr1 - po1) / dvb.y;
        kl += e0 * e0 + e1 * e1;
    }
    __threadfence();
    __syncthreads();
    if (tid == 0) ((volatile int*)g_flag)[gidx] = t + 1;
    #pragma unroll
    for (int o = 16; o > 0; o >>= 1) kl += __shfl_xor_sync(~0u, kl, o);
    if (lane == 0) sh[RED + w] = kl;
    __syncthreads();
    if (tid < 32) {
        float v = (tid < 16) ? sh[RED + tid] : 0.f;
        #pragma unroll
        for (int o = 8; o > 0; o >>= 1) v += __shfl_xor_sync(~0u, v, o);
        if (tid == 0) g_kldpart[t * 64 + gidx] = v;
    }
}

__device__ void p_step(int t, const float* __restrict__ bp2,
                       const float* __restrict__ X, float* sh, int gidx)
{
    unsigned* shu = (unsigned*)sh;
    const int tid = threadIdx.x;
    const int w = tid >> 5, lane = tid & 31, g = lane >> 2, tig = lane & 3;
    const int r0 = gidx * 16;
    const size_t hb = (size_t)t * BATCH * HDIM;

    // ---- step-top prefetches (independent of the z flag) ----
    uint4 br0, br1;
    pf_ld(g_Wp1zT, tid, br0, br1);
    const int sr = tid >> 5, sc4 = (tid & 31) * 4;
    const int sbi = (r0 + sr) >> 3;
    float4 hP = *(const float4*)&g_Hph[hb + (size_t)sbi * HDIM + sc4];    // np=0
    const int bi0 = (r0 + g) >> 3, bi1 = (r0 + g + 8) >> 3;
    float mt0 = g_Mt[t * BATCH + bi0];
    float mt1 = g_Mt[t * BATCH + bi1];
    float2 xv0 = make_float2(0.f, 0.f), xv1 = make_float2(0.f, 0.f);
    float2 biam = make_float2(0.f, 0.f), bial = make_float2(0.f, 0.f);
    if (w < 8) {
        int mc = w * 8 + 2 * tig;
        xv0 = *(const float2*)&X[((size_t)t * BATCH + bi0) * DIN + mc];
        xv1 = *(const float2*)&X[((size_t)t * BATCH + bi1) * DIN + mc];
        biam = *(const float2*)&bp2[mc];
    } else {
        bial = *(const float2*)&bp2[64 + (w - 8) * 8 + 2 * tig];
    }

    // wait for z(t+1), stage to ZB bf16
    if (tid == 0) {
        while (((volatile int*)g_flag)[gidx] < t + 1) __nanosleep(64);
        __threadfence();
    }
    __syncthreads();
    {
        float4 z4 = ldcg4(&g_z[(size_t)(r0 + sr) * ZDIM + sc4]);
        shu[ZB + sr * 68 + (sc4 >> 1)]     = packbf(z4.x, z4.y);
        shu[ZB + sr * 68 + (sc4 >> 1) + 1] = packbf(z4.z, z4.w);
    }
    __syncthreads();
    if (tid == 0) {
        __threadfence();
        ((volatile int*)g_ack)[gidx] = t + 1;
    }

    unsigned za[8][4];
    load_za(shu, g, tig, za);

    float acc[4] = {0.f,0.f,0.f,0.f};
    for (int np = 0; np < 4; np++) {
        float ahz[4] = {0.f,0.f,0.f,0.f};
        #pragma unroll
        for (int st = 0; st < 2; st++) {
            int ss = np * 2 + st;
            unsigned* buf = shu + BB2 + (ss & 1) * 4608;
            pf_st(buf, tid, br0, br1);
            __syncthreads();
            if (ss < 7) {
                const unsigned* s = g_Wp1zT + (size_t)((ss + 1) >> 1) * 128 * 64
                                            + ((ss + 1) & 1) * 32;
                pf_ld(s, tid, br0, br1);
            }
            const unsigned* pB = buf + (w * 8 + g) * 36 + tig;
            #pragma unroll
            for (int kk = 0; kk < 4; kk++)
                mma16(ahz, za[st * 4 + kk], pB[kk*8], pB[kk*8 + 4]);
        }
        {
            int cb = w * 8 + 2 * tig;
            *(float2*)&sh[HZB + g * 132 + cb]       = make_float2(ahz[0], ahz[1]);
            *(float2*)&sh[HZB + (g + 8) * 132 + cb] = make_float2(ahz[2], ahz[3]);
        }
        __syncthreads();
        {   // A staging from prefetched hP + HZB
            float4 z4 = *(const float4*)&sh[HZB + sr * 132 + sc4];
            unsigned u0 = packbf(fmaxf(hP.x + z4.x, 0.f), fmaxf(hP.y + z4.y, 0.f));
            unsigned u1 = packbf(fmaxf(hP.z + z4.z, 0.f), fmaxf(hP.w + z4.w, 0.f));
            *(uint2*)&shu[SAP + sr * 68 + (sc4 >> 1)] = make_uint2(u0, u1);
            if (np < 3)
                hP = *(const float4*)&g_Hph[hb + (size_t)sbi * HDIM + (np + 1) * 128 + sc4];
        }
        __syncthreads();
        #pragma unroll
        for (int st2 = 0; st2 < 2; st2++) {
            const unsigned* pAp = shu + SAP + g * 68 + st2 * 32 + tig;
            const unsigned* pB2 = shu + W2R + (w * 8 + g) * 260 + np * 64 + st2 * 32 + tig;
            #pragma unroll
            for (int kk = 0; kk < 4; kk++) {
                unsigned ap[4] = { pAp[kk*8], pAp[kk*8 + 544], pAp[kk*8 + 4], pAp[kk*8 + 548] };
                mma16(acc, ap, pB2[kk*8], pB2[kk*8 + 4]);
            }
        }
    }

    // ---- NLL epilogue (operands prefetched) ----
    __syncthreads();
    if (w >= 8) {   // logvar warps: export acc+bias (cols 64..127)
        int cb = (w - 8) * 8 + 2 * tig;
        *(float2*)&sh[LVO + g * 68 + cb]       = make_float2(acc[0] + bial.x, acc[1] + bial.y);
        *(float2*)&sh[LVO + (g + 8) * 68 + cb] = make_float2(acc[2] + bial.x, acc[3] + bial.y);
    }
    __syncthreads();
    float local = 0.f;
    if (w < 8) {
        int mc = w * 8 + 2 * tig;
        {
            float2 lv = *(float2*)&sh[LVO + g * 68 + mc];
            float m0 = acc[0] + biam.x, m1 = acc[1] + biam.y;
            float d0 = xv0.x - m0, d1 = xv0.y - m1;
            local += mt0 * 0.5f * (LOG_2PI + lv.x + d0 * d0 * expf(-lv.x));
            local += mt0 * 0.5f * (LOG_2PI + lv.y + d1 * d1 * expf(-lv.y));
        }
        {
            float2 lv = *(float2*)&sh[LVO + (g + 8) * 68 + mc];
            float m0 = acc[2] + biam.x, m1 = acc[3] + biam.y;
            float d0 = xv1.x - m0, d1 = xv1.y - m1;
            local += mt1 * 0.5f * (LOG_2PI + lv.x + d0 * d0 * expf(-lv.x));
            local += mt1 * 0.5f * (LOG_2PI + lv.y + d1 * d1 * expf(-lv.y));
        }
    }
    #pragma unroll
    for (int o = 16; o > 0; o >>= 1) local += __shfl_xor_sync(~0u, local, o);
    if (lane == 0) sh[RED + w] = local;
    __syncthreads();
    if (tid < 32) {
        float v = (tid < 16) ? sh[RED + tid] : 0.f;
        #pragma unroll
        for (int o = 8; o > 0; o >>= 1) v += __shfl_xor_sync(~0u, v, o);
        if (tid == 0) g_reconpart[t * 64 + gidx] = v;
    }
}

__global__ void __launch_bounds__(NTHR, 1)
scan_pairs(const float* __restrict__ bd2, const float* __restrict__ noise,
           const float* __restrict__ bp2, const float* __restrict__ X,
           float* __restrict__ out)
{
    extern __shared__ float sh[];
    unsigned* shu = (unsigned*)sh;
    const int role = blockIdx.x & 1;
    const int gidx = blockIdx.x >> 1;
    const int tid = threadIdx.x;
    const int w = tid >> 5, lane = tid & 31, g = lane >> 2, tig = lane & 3;
    const int r0 = gidx * 16;

    // resident W2 (once per kernel)
    load_w2r(shu, role ? g_Wp2T : g_Wd2T, tid);

    if (role == 0) {
        {   // init ZB (bf16) from z0
            int r = tid >> 5, c4 = (tid & 31) * 4;
            float4 z4 = ldcg4(&g_z[(size_t)(r0 + r) * ZDIM + c4]);
            shu[ZB + r * 68 + (c4 >> 1)]     = packbf(z4.x, z4.y);
            shu[ZB + r * 68 + (c4 >> 1) + 1] = packbf(z4.z, z4.w);
        }
        float zr[4];
        {
            int c = w * 8 + 2 * tig;
            float2 a = ldcg2(&g_z[(size_t)(r0 + g) * ZDIM + c]);
            float2 b = ldcg2(&g_z[(size_t)(r0 + g + 8) * ZDIM + c]);
            zr[0] = a.x; zr[1] = a.y; zr[2] = b.x; zr[3] = b.y;
        }
        __syncthreads();
        for (int t = 0; t < T_STEPS; t++)
            drift_step(t, bd2, noise, sh, zr, gidx, out);
    } else {
        __syncthreads();
        for (int t = 0; t < T_STEPS; t++)
            p_step(t, bp2, X, sh, gidx);
    }
}

// ---------------- outputs ---------------------------------------------------
__global__ void finalize(float* __restrict__ out, int out_size)
{
    int tid = threadIdx.x;   // 256
    if (tid < 64) { g_flag[tid] = 0; g_ack[tid] = 0; }   // reset for graph replay
    float k = 0.f, r = 0.f;
    for (int i = tid; i < T_STEPS * 64; i += 256) k += g_kldpart[i];
    for (int i = tid; i < T_STEPS * 64; i += 256) r += g_reconpart[i];
    __shared__ float rk[256], rr[256];
    rk[tid] = k; rr[tid] = r;
    __syncthreads();
    for (int s = 128; s > 0; s >>= 1) {
        if (tid < s) { rk[tid] += rk[tid + s]; rr[tid] += rr[tid + s]; }
        __syncthreads();
    }
    if (tid == 0) {
        float kld   = rk[0] * (0.5f * DT / (float)BS);
        float recon = rr[0] * (1.f / (float)BS);
        out[out_size - 3] = recon + kld;
        out[out_size - 2] = recon;
        out[out_size - 1] = kld;
    }
}

// ---------------- launch ----------------------------------------------------
extern "C" void kernel_launch(void* const* d_in, const int* in_sizes, int n_in,
                              void* d_out, int out_size)
{
    const float* X     = (const float*)d_in[0];
    const float* M     = (const float*)d_in[1];
    const float* cov   = (const float*)d_in[2];
    const float* ph    = (const float*)d_in[3];
    const float* phpos = (const float*)d_in[4];
    const float* noise = (const float*)d_in[5];
    const float* Wc1 = (const float*)d_in[6],  *bc1 = (const float*)d_in[7];
    const float* Wc2 = (const float*)d_in[8],  *bc2 = (const float*)d_in[9];
    const float* Wd1 = (const float*)d_in[10], *bd1 = (const float*)d_in[11];
    const float* Wd2 = (const float*)d_in[12], *bd2 = (const float*)d_in[13];
    const float* Wf1 = (const float*)d_in[14], *bf1 = (const float*)d_in[15];
    const float* Wf2 = (const float*)d_in[16], *bf2 = (const float*)d_in[17];
    const float* Wp1 = (const float*)d_in[18], *bp1 = (const float*)d_in[19];
    const float* Wp2 = (const float*)d_in[20], *bp2 = (const float*)d_in[21];
    float* out = (float*)d_out;

    unsigned *pWd1zT, *pWd2T, *pWp1zT, *pWp2T;
    cudaGetSymbolAddress((void**)&pWd1zT, g_Wd1zT);
    cudaGetSymbolAddress((void**)&pWd2T,  g_Wd2T);
    cudaGetSymbolAddress((void**)&pWp1zT, g_Wp1zT);
    cudaGetSymbolAddress((void**)&pWp2T,  g_Wp2T);

    static int smem_set = 0;
    if (!smem_set) {
        cudaFuncSetAttribute(scan_pairs,
                             cudaFuncAttributeMaxDynamicSharedMemorySize, SMEM_BYTES);
        smem_set = 1;
    }

    // ---- precompute ----
    z0_kernel<<<BATCH, 128>>>(cov, Wc1, bc1, Wc2, bc2);
    mt_kernel<<<64, 256>>>(M);
    transpose_bf16<<<dim3(16, 8),  256>>>(Wd1 + RDIM * HDIM, pWd1zT, ZDIM, HDIM);
    transpose_bf16<<<dim3(4, 32),  256>>>(Wd2,               pWd2T,  HDIM, ZDIM);
    transpose_bf16<<<dim3(16, 8),  256>>>(Wp1 + RDIM * HDIM, pWp1zT, ZDIM, HDIM);
    transpose_bf16<<<dim3(4, 32),  256>>>(Wp2,               pWp2T,  HDIM, ZDIM);
    gemm_pre4<<<dim3(4, 256, 4), 512>>>(ph, phpos, Wd1, bd1, Wp1, bp1, Wf1, bf1);
    gemm_diff<<<dim3(1, 256), 512>>>(Wf2, bf2);

    // ---- bf16 pairwise scan (resident W2, prefetched operands) ----
    scan_pairs<<<128, NTHR, SMEM_BYTES>>>(bd2, noise, bp2, X, out);

    // ---- losses + flag reset ----
    finalize<<<1, 256>>>(out, out_size);
}